// round 2
// baseline (speedup 1.0000x reference)
#include <cuda_runtime.h>
#include <stdint.h>

// Problem constants (fixed-shape problem: 48x48 grid, regular triangulation)
static constexpr int HH   = 48;
static constexpr int WW   = 48;
static constexpr int N_V  = HH * WW;                                          // 2304
static constexpr int N_E  = HH*(WW-1) + (HH-1)*WW + (HH-1)*(WW-1);            // 6721
static constexpr int N_F  = 2*(HH-1)*(WW-1);                                  // 4418
static constexpr int M_S  = N_V + N_E + N_F;                                  // 13443

// Global scratch (no allocations allowed)
__device__ float              g_vals[M_S];
__device__ unsigned long long g_keys[M_S];
__device__ int                g_rank[M_S];
__device__ int                g_cof0[N_E];
__device__ int                g_cof1[N_E];
__device__ uint4              g_erec[N_E];   // sorted edge records

// Order-preserving map float -> uint32
__device__ __forceinline__ unsigned int fsort(float x) {
    unsigned int u = __float_as_uint(x);
    return (u & 0x80000000u) ? ~u : (u | 0x80000000u);
}

// ---------------------------------------------------------------------------
// K1: per-simplex filtration values + sort keys; init coface arrays; zero out
// ---------------------------------------------------------------------------
__global__ void k_vals(const float* __restrict__ img,
                       const int*   __restrict__ edges,
                       const int*   __restrict__ tris,
                       float* __restrict__ out, int out_n)
{
    int s   = blockIdx.x * blockDim.x + threadIdx.x;
    int gsz = gridDim.x * blockDim.x;
    for (int o = s; o < out_n; o += gsz) out[o] = 0.0f;   // clear poisoned output
    if (s >= M_S) return;

    float v;
    if (s < N_V) {
        v = img[s];
    } else if (s < N_V + N_E) {
        int e = s - N_V;
        v = fmaxf(img[edges[2*e]], img[edges[2*e + 1]]);
        g_cof0[e] = 0x7fffffff;
        g_cof1[e] = -1;
    } else {
        int t = s - N_V - N_E;
        float mx = -__int_as_float(0x7f800000);
        #pragma unroll
        for (int k = 0; k < 3; k++) {
            int e = tris[3*t + k];
            mx = fmaxf(mx, fmaxf(img[edges[2*e]], img[edges[2*e + 1]]));
        }
        v = mx;
    }
    g_vals[s] = v;
    // key = (sortable value, original index); dim is monotone in index, so
    // this reproduces lexsort((dims, vals)) exactly.
    g_keys[s] = ((unsigned long long)fsort(v) << 32) | (unsigned int)s;
}

// ---------------------------------------------------------------------------
// K2: edge -> triangle coface map (deterministic atomicMin/Max)
// ---------------------------------------------------------------------------
__global__ void k_cof(const int* __restrict__ tris)
{
    int t = blockIdx.x * blockDim.x + threadIdx.x;
    if (t >= N_F) return;
    #pragma unroll
    for (int k = 0; k < 3; k++) {
        int e = tris[3*t + k];
        atomicMin(&g_cof0[e], t);
        atomicMax(&g_cof1[e], t);
    }
}

// ---------------------------------------------------------------------------
// K3: rank by counting over smem chunks. Segmented inner loops so the
// edge-subrange (erank) test is hoisted out of the hot loop.
// ---------------------------------------------------------------------------
static constexpr int RCHUNK = 4096;

__global__ void k_rank(const int* __restrict__ edges)
{
    __shared__ unsigned long long sk[RCHUNK];
    int  s   = blockIdx.x * blockDim.x + threadIdx.x;
    bool act = (s < M_S);
    unsigned long long my = act ? g_keys[s] : 0ULL;

    int rank = 0, erank = 0;
    for (int cb = 0; cb < M_S; cb += RCHUNK) {
        int cnt = min(RCHUNK, M_S - cb);
        __syncthreads();
        for (int j = threadIdx.x; j < cnt; j += blockDim.x) sk[j] = g_keys[cb + j];
        __syncthreads();
        if (act) {
            int jLo = max(0, N_V - cb);
            int jHi = min(cnt, N_V + N_E - cb);
            if (jLo > cnt) jLo = cnt;
            if (jHi < jLo) jHi = jLo;
            int j = 0;
            #pragma unroll 4
            for (; j < jLo; j++) rank += (sk[j] < my);
            #pragma unroll 4
            for (; j < jHi; j++) { bool lt = sk[j] < my; rank += lt; erank += lt; }
            #pragma unroll 4
            for (; j < cnt; j++) rank += (sk[j] < my);
        }
    }
    if (!act) return;
    g_rank[s] = rank;

    if (s >= N_V && s < N_V + N_E) {
        int e  = s - N_V;
        int u  = edges[2*e], v = edges[2*e + 1];
        int c0 = g_cof0[e],  c1 = g_cof1[e];
        uint4 r;
        r.x = (unsigned)u | ((unsigned)v << 16);
        r.y = __float_as_uint(g_vals[s]);
        r.z = (unsigned)rank;
        r.w = (unsigned)c0 | ((unsigned)c1 << 16);
        g_erec[erank] = r;
    }
}

// ---------------------------------------------------------------------------
// K4: single block, warp-specialized:
//   warp 0: dim-0 processor (pre-find lanes + lane0 serial unions)
//   warp 1: dim-1 processor (dual UF, reversed order)
//   warps 2,3: background path-compressors for p0
//   warps 4,5: background path-compressors for p1
//   warps 6,7: exit after staging
// bR/bV at roots are IMMUTABLE (elder/survivor stays root), so pre-loaded
// values stay valid as long as the pre-found root is still a root.
// ---------------------------------------------------------------------------
static constexpr int SMEM_BYTES = N_E*16 + N_V*12 + (N_F + 1)*12 + 32;

__device__ __forceinline__ int chase(volatile int* p, int x) {
    int px = p[x];
    while (px != x) { x = px; px = p[x]; }
    return x;
}

__global__ void __launch_bounds__(256, 1)
k_pair(const float* __restrict__ img, float* __restrict__ out)
{
    extern __shared__ int smbuf[];
    uint4* rec = (uint4*)smbuf;                  // [N_E]
    int*   p0  = (int*)(rec + N_E);              // [N_V]
    int*   bR0 = p0 + N_V;                       // [N_V]   immutable after init
    float* bV0 = (float*)(bR0 + N_V);            // [N_V]   immutable after init
    int*   p1  = (int*)(bV0 + N_V);              // [N_F+1]
    int*   bR1 = p1 + (N_F + 1);                 // immutable
    float* bV1 = (float*)(bR1 + (N_F + 1));      // immutable
    volatile int* done = (volatile int*)(bV1 + (N_F + 1));  // [2]
    __shared__ float smin[256], smax[256];

    volatile int* p0v = (volatile int*)p0;
    volatile int* p1v = (volatile int*)p1;

    int tid  = threadIdx.x;
    int wid  = tid >> 5;
    int lane = tid & 31;

    for (int i = tid; i < N_E; i += 256) rec[i] = g_erec[i];
    for (int v = tid; v < N_V; v += 256) {
        p0[v] = v; bR0[v] = g_rank[v]; bV0[v] = img[v];
    }
    for (int t = tid; t < N_F; t += 256) {
        p1[t] = t; bR1[t] = g_rank[N_V + N_E + t]; bV1[t] = g_vals[N_V + N_E + t];
    }
    if (tid == 0) {
        p1[N_F] = N_F; bR1[N_F] = M_S; bV1[N_F] = 0.0f;
        done[0] = 0; done[1] = 0;
    }

    // essential H0: min/max over vertex values (all simplex values are vertex maxes)
    float inf = __int_as_float(0x7f800000);
    float lmin = inf, lmax = -inf;
    for (int i = tid; i < N_V; i += 256) {
        float x = img[i];
        lmin = fminf(lmin, x); lmax = fmaxf(lmax, x);
    }
    smin[tid] = lmin; smax[tid] = lmax;
    __syncthreads();
    for (int st = 128; st > 0; st >>= 1) {
        if (tid < st) {
            smin[tid] = fminf(smin[tid], smin[tid + st]);
            smax[tid] = fmaxf(smax[tid], smax[tid + st]);
        }
        __syncthreads();
    }
    if (tid == 0) { out[0] = smin[0]; out[1] = smax[0]; }
    __syncthreads();   // last block-wide barrier; roles diverge below

    const unsigned FULL = 0xffffffffu;
    const int NB = (N_E + 31) / 32;

    if (wid == 0) {
        // ================= dim 0: forward order =================
        for (int b = 0; b < NB; b++) {
            int i = b * 32 + lane;
            float EV = 0.0f, VU = 0.0f, VV = 0.0f;
            int RU = 0, RV = 0, BU = -1, BV = -1;
            if (i < N_E) {
                uint4 r = rec[i];
                EV = __uint_as_float(r.y);
                int u = (int)(r.x & 0xffffu), v = (int)(r.x >> 16);
                RU = chase(p0v, u);  BU = bR0[RU];  VU = bV0[RU];
                RV = chase(p0v, v);  BV = bR0[RV];  VV = bV0[RV];
            }
            int lim = min(32, N_E - b * 32);
            for (int k = 0; k < lim; k++) {
                float ev = __shfl_sync(FULL, EV, k);
                float vu = __shfl_sync(FULL, VU, k);
                float vv = __shfl_sync(FULL, VV, k);
                int ru = __shfl_sync(FULL, RU, k);
                int rv = __shfl_sync(FULL, RV, k);
                int bu = __shfl_sync(FULL, BU, k);
                int bv = __shfl_sync(FULL, BV, k);
                if (lane == 0) {
                    int pu = p0v[ru];
                    int pv = p0v[rv];
                    while (pu != ru) { ru = pu; pu = p0v[ru]; bu = -1; }
                    while (pv != rv) { rv = pv; pv = p0v[rv]; bv = -1; }
                    if (ru != rv) {
                        if (bu < 0) { bu = bR0[ru]; vu = bV0[ru]; }
                        if (bv < 0) { bv = bR0[rv]; vv = bV0[rv]; }
                        int ry; float vy; int row; int elder;
                        if (bu > bv) { ry = ru; row = bu; vy = vu; elder = rv; }
                        else         { ry = rv; row = bv; vy = vv; elder = ru; }
                        out[(size_t)row * 2]     = vy;  // birth
                        out[(size_t)row * 2 + 1] = ev;  // death
                        p0v[ry] = elder;
                    }
                }
            }
            __syncwarp(FULL);
        }
        if (lane == 0) done[0] = 1;
    } else if (wid == 1) {
        // ================= dim 1: reversed order on dual =================
        const size_t base = (size_t)2 * M_S;
        for (int b = 0; b < NB; b++) {
            int i = N_E - 1 - (b * 32 + lane);
            float EV = 0.0f, VU = 0.0f, VV = 0.0f;
            int RU = 0, RV = 0, BU = -1, BV = -1, RZ = 0;
            if (i >= 0) {
                uint4 r = rec[i];
                EV = __uint_as_float(r.y);
                RZ = (int)r.z;
                int c0 = (int)(r.w & 0xffffu), c1 = (int)(r.w >> 16);
                int a = c0;
                int bnode = (c1 == c0) ? N_F : c1;
                RU = chase(p1v, a);      BU = bR1[RU];  VU = bV1[RU];
                RV = chase(p1v, bnode);  BV = bR1[RV];  VV = bV1[RV];
            }
            int lim = min(32, N_E - b * 32);
            for (int k = 0; k < lim; k++) {
                float ev = __shfl_sync(FULL, EV, k);
                float vu = __shfl_sync(FULL, VU, k);
                float vv = __shfl_sync(FULL, VV, k);
                int ru = __shfl_sync(FULL, RU, k);
                int rv = __shfl_sync(FULL, RV, k);
                int bu = __shfl_sync(FULL, BU, k);
                int bv = __shfl_sync(FULL, BV, k);
                int rz = __shfl_sync(FULL, RZ, k);
                if (lane == 0) {
                    int pu = p1v[ru];
                    int pv = p1v[rv];
                    while (pu != ru) { ru = pu; pu = p1v[ru]; bu = -1; }
                    while (pv != rv) { rv = pv; pv = p1v[rv]; bv = -1; }
                    if (ru != rv) {
                        if (bu < 0) { bu = bR1[ru]; vu = bV1[ru]; }
                        if (bv < 0) { bv = bR1[rv]; vv = bV1[rv]; }
                        // survivor = larger forward rank (elder in reversed order)
                        int dying; float vd;
                        int surv;
                        if (bu < bv) { dying = ru; vd = vu; surv = rv; }
                        else         { dying = rv; vd = vv; surv = ru; }
                        out[base + (size_t)rz * 2]     = ev;  // birth = edge value
                        out[base + (size_t)rz * 2 + 1] = vd;  // death = triangle value
                        p1v[dying] = surv;
                    }
                }
            }
            __syncwarp(FULL);
        }
        if (lane == 0) done[1] = 1;
    } else if (wid == 2 || wid == 3) {
        // ============ background compressors for p0 ============
        int start = (wid - 2) * 32 + lane;   // warps 2,3 interleave via stride 64
        while (!done[0]) {
            for (int i = start; i < N_V; i += 64) {
                int pi = p0v[i];
                if (pi == i) continue;
                int r = pi, pr = p0v[r], hops = 0;
                while (pr != r && hops < 16) { r = pr; pr = p0v[r]; hops++; }
                if (r != pi) p0v[i] = r;
            }
        }
    } else if (wid == 4 || wid == 5) {
        // ============ background compressors for p1 ============
        int start = (wid - 4) * 32 + lane;
        int n1 = N_F + 1;
        while (!done[1]) {
            for (int i = start; i < n1; i += 64) {
                int pi = p1v[i];
                if (pi == i) continue;
                int r = pi, pr = p1v[r], hops = 0;
                while (pr != r && hops < 16) { r = pr; pr = p1v[r]; hops++; }
                if (r != pi) p1v[i] = r;
            }
        }
    }
    // warps 6,7 exit
}

// ---------------------------------------------------------------------------
extern "C" void kernel_launch(void* const* d_in, const int* in_sizes, int n_in,
                              void* d_out, int out_size)
{
    const float* img   = (const float*)d_in[0];
    const int*   edges = (const int*)d_in[1];
    const int*   tris  = (const int*)d_in[2];
    float*       out   = (float*)d_out;

    cudaFuncSetAttribute(k_pair, cudaFuncAttributeMaxDynamicSharedMemorySize, SMEM_BYTES);

    k_vals<<<(M_S + 255) / 256, 256>>>(img, edges, tris, out, out_size);
    k_cof <<<(N_F + 255) / 256, 256>>>(tris);
    k_rank<<<(M_S + 255) / 256, 256>>>(edges);
    k_pair<<<1, 256, SMEM_BYTES>>>(img, out);
}

// round 4
// speedup vs baseline: 5.9028x; 5.9028x over previous
#include <cuda_runtime.h>
#include <stdint.h>

// Problem constants (fixed-shape problem: 48x48 grid, regular triangulation)
static constexpr int HH   = 48;
static constexpr int WW   = 48;
static constexpr int N_V  = HH * WW;                                          // 2304
static constexpr int N_E  = HH*(WW-1) + (HH-1)*WW + (HH-1)*(WW-1);            // 6721
static constexpr int N_F  = 2*(HH-1)*(WW-1);                                  // 4418
static constexpr int M_S  = N_V + N_E + N_F;                                  // 13443

typedef unsigned long long u64;
static constexpr u64 LOW48 = 0x0000FFFFFFFFFFFFULL;

// Global scratch (no allocations allowed)
__device__ float g_vals[M_S];
__device__ u64   g_keys[M_S];
__device__ int   g_rank[M_S];
__device__ int   g_cof0[N_E];
__device__ int   g_cof1[N_E];
__device__ uint4 g_erec[N_E];   // sorted edge records

// Order-preserving map float -> uint32
__device__ __forceinline__ unsigned int fsort(float x) {
    unsigned int u = __float_as_uint(x);
    return (u & 0x80000000u) ? ~u : (u | 0x80000000u);
}

// ---------------------------------------------------------------------------
// K1: per-simplex filtration values + sort keys; init coface arrays; zero out
// ---------------------------------------------------------------------------
__global__ void k_vals(const float* __restrict__ img,
                       const int*   __restrict__ edges,
                       const int*   __restrict__ tris,
                       float* __restrict__ out, int out_n)
{
    int s   = blockIdx.x * blockDim.x + threadIdx.x;
    int gsz = gridDim.x * blockDim.x;
    for (int o = s; o < out_n; o += gsz) out[o] = 0.0f;   // clear poisoned output
    if (s >= M_S) return;

    float v;
    if (s < N_V) {
        v = img[s];
    } else if (s < N_V + N_E) {
        int e = s - N_V;
        v = fmaxf(img[edges[2*e]], img[edges[2*e + 1]]);
        g_cof0[e] = 0x7fffffff;
        g_cof1[e] = -1;
    } else {
        int t = s - N_V - N_E;
        float mx = -__int_as_float(0x7f800000);
        #pragma unroll
        for (int k = 0; k < 3; k++) {
            int e = tris[3*t + k];
            mx = fmaxf(mx, fmaxf(img[edges[2*e]], img[edges[2*e + 1]]));
        }
        v = mx;
    }
    g_vals[s] = v;
    // key = (sortable value, original index); dim is monotone in index, so
    // this reproduces lexsort((dims, vals)) exactly.
    g_keys[s] = ((u64)fsort(v) << 32) | (unsigned int)s;
}

// ---------------------------------------------------------------------------
// K2: edge -> triangle coface map (deterministic atomicMin/Max)
// ---------------------------------------------------------------------------
__global__ void k_cof(const int* __restrict__ tris)
{
    int t = blockIdx.x * blockDim.x + threadIdx.x;
    if (t >= N_F) return;
    #pragma unroll
    for (int k = 0; k < 3; k++) {
        int e = tris[3*t + k];
        atomicMin(&g_cof0[e], t);
        atomicMax(&g_cof1[e], t);
    }
}

// ---------------------------------------------------------------------------
// K3: rank by counting over smem chunks (all keys distinct).
// ---------------------------------------------------------------------------
static constexpr int RCHUNK = 4096;

__global__ void k_rank(const int* __restrict__ edges)
{
    __shared__ u64 sk[RCHUNK];
    int  s   = blockIdx.x * blockDim.x + threadIdx.x;
    bool act = (s < M_S);
    u64 my = act ? g_keys[s] : 0ULL;

    int rank = 0, erank = 0;
    for (int cb = 0; cb < M_S; cb += RCHUNK) {
        int cnt = min(RCHUNK, M_S - cb);
        __syncthreads();
        for (int j = threadIdx.x; j < cnt; j += blockDim.x) sk[j] = g_keys[cb + j];
        __syncthreads();
        if (act) {
            int jLo = max(0, min(cnt, N_V - cb));
            int jHi = max(jLo, min(cnt, N_V + N_E - cb));
            int j = 0;
            #pragma unroll 4
            for (; j < jLo; j++) rank += (sk[j] < my);
            #pragma unroll 4
            for (; j < jHi; j++) { bool lt = sk[j] < my; rank += lt; erank += lt; }
            #pragma unroll 4
            for (; j < cnt; j++) rank += (sk[j] < my);
        }
    }
    if (!act) return;
    g_rank[s] = rank;

    if (s >= N_V && s < N_V + N_E) {
        int e  = s - N_V;
        int u  = edges[2*e], v = edges[2*e + 1];
        int c0 = g_cof0[e],  c1 = g_cof1[e];
        uint4 r;
        r.x = (unsigned)u | ((unsigned)v << 16);   // endpoints (< 2304, 16b each)
        r.y = __float_as_uint(g_vals[s]);          // edge value
        r.z = (unsigned)rank;                      // global rank of this edge
        r.w = (unsigned)c0 | ((unsigned)c1 << 16); // cofaces; c0==c1 => boundary
        g_erec[erank] = r;
    }
}

// ---------------------------------------------------------------------------
// K4: single block. Packed-word union-find, one serial thread per dimension
// (tid 0 = dim0 forward, tid 32 = dim1 reversed dual), software-pipelined.
// Node word: [parent:16 | birth-rank:16 | birth-val:32]. Root <=> parent==self.
// Rank/val fields at a live root are immutable; halving writes keep low bits
// (don't-care for non-roots). Single-writer per UF => plain smem, program order.
// SMEM layout: rec (uint4, 16B-aligned) FIRST, then the 8B packed arrays.
// ---------------------------------------------------------------------------
static constexpr int SMEM_BYTES = N_E*16 + N_V*8 + (N_F + 2)*8;

// find root starting from x with preloaded word w (parent pointer may be stale
// but is always an ancestor => safe). Path-halving.
__device__ __forceinline__ u64 pfind(u64* __restrict__ pk, int x, u64 w, int& root)
{
    for (;;) {
        int par = (int)(w >> 48);
        if (par == x) { root = x; return w; }
        u64 wp = pk[par];
        int gp = (int)(wp >> 48);
        if (gp != par) pk[x] = (w & LOW48) | ((u64)gp << 48);  // halve
        x = par; w = wp;
    }
}

__global__ void __launch_bounds__(256, 1)
k_pair(const float* __restrict__ img, float* __restrict__ out)
{
    extern __shared__ uint4 smq[];
    uint4* rec = smq;                        // [N_E]   offset 0, 16B aligned
    u64*   pk0 = (u64*)(rec + N_E);          // [N_V]   8B aligned
    u64*   pk1 = pk0 + N_V;                  // [N_F+1]
    __shared__ float smin[256], smax[256];

    int tid = threadIdx.x;

    for (int i = tid; i < N_E; i += 256) rec[i] = g_erec[i];
    for (int v = tid; v < N_V; v += 256)
        pk0[v] = ((u64)v << 48) | ((u64)(unsigned)g_rank[v] << 32)
               | (u64)__float_as_uint(img[v]);
    for (int t = tid; t < N_F; t += 256)
        pk1[t] = ((u64)t << 48) | ((u64)(unsigned)g_rank[N_V + N_E + t] << 32)
               | (u64)__float_as_uint(g_vals[N_V + N_E + t]);
    if (tid == 0)
        pk1[N_F] = ((u64)N_F << 48) | ((u64)(unsigned)M_S << 32);

    // essential H0 (row 0): [global min, global max] of vertex values
    float inf = __int_as_float(0x7f800000);
    float lmin = inf, lmax = -inf;
    for (int i = tid; i < N_V; i += 256) {
        float x = img[i];
        lmin = fminf(lmin, x); lmax = fmaxf(lmax, x);
    }
    smin[tid] = lmin; smax[tid] = lmax;
    __syncthreads();
    for (int st = 128; st > 0; st >>= 1) {
        if (tid < st) {
            smin[tid] = fminf(smin[tid], smin[tid + st]);
            smax[tid] = fmaxf(smax[tid], smax[tid + st]);
        }
        __syncthreads();
    }
    if (tid == 0) { out[0] = smin[0]; out[1] = smax[0]; }
    __syncthreads();

    if (tid == 0) {
        // ================= dim 0: forward order =================
        int lastIdx = -1; u64 lastW = 0;
        uint4 rc = rec[0];
        int u = (int)(rc.x & 0xffffu), v = (int)(rc.x >> 16);
        u64 wu = pk0[u], wv = pk0[v];
        for (int i = 0; i < N_E; i++) {
            // prefetch next edge (off the dependent chain)
            uint4 rn = make_uint4(0,0,0,0);
            int un = 0, vn = 0; u64 wun = 0, wvn = 0;
            if (i + 1 < N_E) {
                rn  = rec[i + 1];
                un  = (int)(rn.x & 0xffffu); vn = (int)(rn.x >> 16);
                wun = pk0[un]; wvn = pk0[vn];
            }
            // patch against previous iteration's union write
            if (u == lastIdx) wu = lastW;
            if (v == lastIdx) wv = lastW;

            int ru, rv;
            u64 wru = pfind(pk0, u, wu, ru);
            u64 wrv = pfind(pk0, v, wv, rv);
            int nl = -1; u64 nw = 0;
            if (ru != rv) {
                int bu = (int)((wru >> 32) & 0xffffu);
                int bv = (int)((wrv >> 32) & 0xffffu);
                int y, elder, row; u64 wy;
                if (bu > bv) { y = ru; wy = wru; row = bu; elder = rv; }
                else         { y = rv; wy = wrv; row = bv; elder = ru; }
                out[(size_t)row * 2]     = __uint_as_float((unsigned)(wy & 0xffffffffu));
                out[(size_t)row * 2 + 1] = __uint_as_float(rc.y);
                nw = (wy & LOW48) | ((u64)elder << 48);
                pk0[y] = nw; nl = y;
            }
            lastIdx = nl; lastW = nw;
            rc = rn; u = un; v = vn; wu = wun; wv = wvn;
        }
    } else if (tid == 32) {
        // ======== dim 1: reversed order on dual (triangles + outer face) ========
        const size_t base = (size_t)2 * M_S;
        int lastIdx = -1; u64 lastW = 0;
        uint4 rc = rec[N_E - 1];
        int c0 = (int)(rc.w & 0xffffu), c1 = (int)(rc.w >> 16);
        int a = c0, b = (c1 == c0) ? N_F : c1;
        u64 wa = pk1[a], wb = pk1[b];
        for (int i = N_E - 1; i >= 0; i--) {
            uint4 rn = make_uint4(0,0,0,0);
            int an = 0, bn = 0; u64 wan = 0, wbn = 0;
            if (i > 0) {
                rn = rec[i - 1];
                int d0 = (int)(rn.w & 0xffffu), d1 = (int)(rn.w >> 16);
                an = d0; bn = (d1 == d0) ? N_F : d1;
                wan = pk1[an]; wbn = pk1[bn];
            }
            if (a == lastIdx) wa = lastW;
            if (b == lastIdx) wb = lastW;

            int ra, rb;
            u64 wra = pfind(pk1, a, wa, ra);
            u64 wrb = pfind(pk1, b, wb, rb);
            int nl = -1; u64 nw = 0;
            if (ra != rb) {
                int ba = (int)((wra >> 32) & 0xffffu);
                int bb = (int)((wrb >> 32) & 0xffffu);
                // survivor = larger forward rank (elder in reversed order)
                int y, surv; u64 wy;
                if (ba < bb) { y = ra; wy = wra; surv = rb; }
                else         { y = rb; wy = wrb; surv = ra; }
                int row = (int)rc.z;
                out[base + (size_t)row * 2]     = __uint_as_float(rc.y);
                out[base + (size_t)row * 2 + 1] = __uint_as_float((unsigned)(wy & 0xffffffffu));
                nw = (wy & LOW48) | ((u64)surv << 48);
                pk1[y] = nw; nl = y;
            }
            lastIdx = nl; lastW = nw;
            rc = rn; a = an; b = bn; wa = wan; wb = wbn;
        }
    }
    // all other threads exit
}

// ---------------------------------------------------------------------------
extern "C" void kernel_launch(void* const* d_in, const int* in_sizes, int n_in,
                              void* d_out, int out_size)
{
    const float* img   = (const float*)d_in[0];
    const int*   edges = (const int*)d_in[1];
    const int*   tris  = (const int*)d_in[2];
    float*       out   = (float*)d_out;

    cudaFuncSetAttribute(k_pair, cudaFuncAttributeMaxDynamicSharedMemorySize, SMEM_BYTES);

    k_vals<<<(M_S + 255) / 256, 256>>>(img, edges, tris, out, out_size);
    k_cof <<<(N_F + 255) / 256, 256>>>(tris);
    k_rank<<<(M_S + 255) / 256, 256>>>(edges);
    k_pair<<<1, 256, SMEM_BYTES>>>(img, out);
}

// round 5
// speedup vs baseline: 9.7956x; 1.6595x over previous
#include <cuda_runtime.h>
#include <stdint.h>

// Problem constants (fixed-shape problem: 48x48 grid, regular triangulation)
static constexpr int HH   = 48;
static constexpr int WW   = 48;
static constexpr int N_V  = HH * WW;                                          // 2304
static constexpr int N_E  = HH*(WW-1) + (HH-1)*WW + (HH-1)*(WW-1);            // 6721
static constexpr int N_F  = 2*(HH-1)*(WW-1);                                  // 4418
static constexpr int M_S  = N_V + N_E + N_F;                                  // 13443
static constexpr int NT   = N_V - 1;                                          // 2303 MST edges
static constexpr int ND   = N_E - NT;                                         // 4418 dual-tree edges

typedef unsigned long long u64;
static constexpr u64 LOW48 = 0x0000FFFFFFFFFFFFULL;

// Global scratch (no allocations allowed)
__device__ float g_vals[M_S];
__device__ u64   g_keys[M_S];
__device__ int   g_rank[M_S];
__device__ int   g_cof0[N_E];
__device__ int   g_cof1[N_E];
__device__ uint4 g_erec[N_E];   // sorted edge records

// Order-preserving map float -> uint32
__device__ __forceinline__ unsigned int fsort(float x) {
    unsigned int u = __float_as_uint(x);
    return (u & 0x80000000u) ? ~u : (u | 0x80000000u);
}

// ---------------------------------------------------------------------------
// K1: per-simplex filtration values + sort keys; init coface arrays; zero out
// ---------------------------------------------------------------------------
__global__ void k_vals(const float* __restrict__ img,
                       const int*   __restrict__ edges,
                       const int*   __restrict__ tris,
                       float* __restrict__ out, int out_n)
{
    int s   = blockIdx.x * blockDim.x + threadIdx.x;
    int gsz = gridDim.x * blockDim.x;
    for (int o = s; o < out_n; o += gsz) out[o] = 0.0f;   // clear poisoned output
    if (s >= M_S) return;

    float v;
    if (s < N_V) {
        v = img[s];
    } else if (s < N_V + N_E) {
        int e = s - N_V;
        v = fmaxf(img[edges[2*e]], img[edges[2*e + 1]]);
        g_cof0[e] = 0x7fffffff;
        g_cof1[e] = -1;
    } else {
        int t = s - N_V - N_E;
        float mx = -__int_as_float(0x7f800000);
        #pragma unroll
        for (int k = 0; k < 3; k++) {
            int e = tris[3*t + k];
            mx = fmaxf(mx, fmaxf(img[edges[2*e]], img[edges[2*e + 1]]));
        }
        v = mx;
    }
    g_vals[s] = v;
    // key = (sortable value, original index); dim is monotone in index, so
    // this reproduces lexsort((dims, vals)) exactly.
    g_keys[s] = ((u64)fsort(v) << 32) | (unsigned int)s;
}

// ---------------------------------------------------------------------------
// K2: edge -> triangle coface map (deterministic atomicMin/Max)
// ---------------------------------------------------------------------------
__global__ void k_cof(const int* __restrict__ tris)
{
    int t = blockIdx.x * blockDim.x + threadIdx.x;
    if (t >= N_F) return;
    #pragma unroll
    for (int k = 0; k < 3; k++) {
        int e = tris[3*t + k];
        atomicMin(&g_cof0[e], t);
        atomicMax(&g_cof1[e], t);
    }
}

// ---------------------------------------------------------------------------
// K3: rank by counting over smem chunks (all keys distinct).
// ---------------------------------------------------------------------------
static constexpr int RCHUNK = 4096;

__global__ void k_rank(const int* __restrict__ edges)
{
    __shared__ u64 sk[RCHUNK];
    int  s   = blockIdx.x * blockDim.x + threadIdx.x;
    bool act = (s < M_S);
    u64 my = act ? g_keys[s] : 0ULL;

    int rank = 0, erank = 0;
    for (int cb = 0; cb < M_S; cb += RCHUNK) {
        int cnt = min(RCHUNK, M_S - cb);
        __syncthreads();
        for (int j = threadIdx.x; j < cnt; j += blockDim.x) sk[j] = g_keys[cb + j];
        __syncthreads();
        if (act) {
            int jLo = max(0, min(cnt, N_V - cb));
            int jHi = max(jLo, min(cnt, N_V + N_E - cb));
            int j = 0;
            #pragma unroll 4
            for (; j < jLo; j++) rank += (sk[j] < my);
            #pragma unroll 4
            for (; j < jHi; j++) { bool lt = sk[j] < my; rank += lt; erank += lt; }
            #pragma unroll 4
            for (; j < cnt; j++) rank += (sk[j] < my);
        }
    }
    if (!act) return;
    g_rank[s] = rank;

    if (s >= N_V && s < N_V + N_E) {
        int e  = s - N_V;
        int u  = edges[2*e], v = edges[2*e + 1];
        int c0 = g_cof0[e],  c1 = g_cof1[e];
        uint4 r;
        r.x = (unsigned)u | ((unsigned)v << 16);   // endpoints (< 2304, 16b each)
        r.y = __float_as_uint(g_vals[s]);          // edge value
        r.z = (unsigned)rank;                      // global rank of this edge
        r.w = (unsigned)c0 | ((unsigned)c1 << 16); // cofaces; c0==c1 => boundary
        g_erec[erank] = r;
    }
}

// ---------------------------------------------------------------------------
// K4: single block, 512 threads.
// Phase A (parallel): stage rec; Borůvka MST over primal graph (weights =
//   sorted edge index) -> tb[e] marks tree edges; complement = dual max-ST.
// Phase B (parallel): order-preserving compaction into treeL (increasing) and
//   dualR (decreasing); init packed UF arrays; min/max reduction.
// Phase C (serial x2, concurrent warps): tid0 = dim0 over treeL (every edge a
//   union); tid32 = dim1 over dualR (every edge a dual union).
// Node word: [parent:16 | birth-rank:16 | birth-val:32]; root <=> parent==self.
// ---------------------------------------------------------------------------
static constexpr int SMEM_BYTES =
      N_E*16            // rec
    + N_V*8             // pk0
    + 4420*8            // pk1 (N_F+1, padded)
    + N_V*4             // par
    + N_V*4             // best
    + (NT+1)*2 + 2      // treeL + sentinel (padded to 4B)
    + (ND+2)*2          // dualR + sentinel
    + ((N_E+3)&~3);     // tb bytes

// full find with path halving; w = starting word for x (parent may be stale
// but always an ancestor)
__device__ __forceinline__ u64 pfind(u64* __restrict__ pk, int x, u64 w, int& root)
{
    for (;;) {
        int par = (int)(w >> 48);
        if (par == x) { root = x; return w; }
        u64 wp = pk[par];
        int gp = (int)(wp >> 48);
        if (gp != par) pk[x] = (w & LOW48) | ((u64)gp << 48);  // halve
        x = par; w = wp;
    }
}

__global__ void __launch_bounds__(512, 1)
k_pair(const float* __restrict__ img, float* __restrict__ out)
{
    extern __shared__ uint4 smq[];
    uint4*  rec   = smq;                                  // [N_E]
    u64*    pk0   = (u64*)(rec + N_E);                    // [N_V]
    u64*    pk1   = pk0 + N_V;                            // [4420]
    int*    par   = (int*)(pk1 + 4420);                   // [N_V]
    int*    best  = par + N_V;                            // [N_V]
    ushort* treeL = (ushort*)(best + N_V);                // [NT+1] (+pad)
    ushort* dualR = treeL + (NT + 1) + 1;                 // [ND+2]
    unsigned char* tb = (unsigned char*)(dualR + (ND + 2)); // [N_E]
    int*    par2  = (int*)pk1;   // snapshot buffer, reused before pk1 init

    __shared__ float s_min[512], s_max[512];
    __shared__ int   s_scan[512];
    __shared__ int   s_changed;

    int tid = threadIdx.x;

    // ---- stage records, init Borůvka state ----
    for (int i = tid; i < N_E; i += 512) { rec[i] = g_erec[i]; tb[i] = 0; }
    for (int v = tid; v < N_V; v += 512) par[v] = v;
    __syncthreads();

    // ---- Borůvka MST (weight = sorted edge index, all distinct) ----
    for (int round = 0; round < 20; round++) {
        if (tid == 0) s_changed = 0;
        for (int v = tid; v < N_V; v += 512) best[v] = 0x7fffffff;
        __syncthreads();
        // candidates: par[] is fully compressed -> root = par[x]
        for (int e = tid; e < N_E; e += 512) {
            unsigned ex = rec[e].x;
            int ru = par[(int)(ex & 0xffffu)];
            int rv = par[(int)(ex >> 16)];
            if (ru != rv) { atomicMin(&best[ru], e); atomicMin(&best[rv], e); }
        }
        // snapshot roots for deterministic hooking
        for (int v = tid; v < N_V; v += 512) par2[v] = par[v];
        __syncthreads();
        // hook: root r attaches along its best edge; mutual ties -> larger hooks
        for (int v = tid; v < N_V; v += 512) {
            if (par2[v] == v) {
                int e = best[v];
                if (e != 0x7fffffff) {
                    unsigned ex = rec[e].x;
                    int ra = par2[(int)(ex & 0xffffu)];
                    int rb = par2[(int)(ex >> 16)];
                    int other = (ra == v) ? rb : ra;
                    bool mutual = (best[other] == e);
                    if (!mutual || v > other) {
                        par[v] = other;
                        tb[e]  = 1;
                        s_changed = 1;
                    }
                }
            }
        }
        __syncthreads();
        // full compression (chase to root; concurrent rootward writes are safe)
        for (int v = tid; v < N_V; v += 512) {
            int r = par[v], pr = par[r];
            while (pr != r) { r = pr; pr = par[r]; }
            par[v] = r;
        }
        __syncthreads();
        if (!s_changed) break;
    }

    // ---- order-preserving compaction: tree -> treeL (inc), non-tree -> dualR (dec) ----
    {
        const int CH = 14;                       // 512*14 = 7168 >= N_E
        int c0 = tid * CH;
        int c1 = min(N_E, c0 + CH);
        if (c0 > N_E) c0 = N_E;
        int cnt = 0;
        for (int e = c0; e < c1; e++) cnt += tb[e];
        s_scan[tid] = cnt;
        __syncthreads();
        for (int off = 1; off < 512; off <<= 1) {
            int x = s_scan[tid];
            int y = (tid >= off) ? s_scan[tid - off] : 0;
            __syncthreads();
            s_scan[tid] = x + y;
            __syncthreads();
        }
        int excl = s_scan[tid] - cnt;
        int tpos = excl;
        int dpos = c0 - excl;
        for (int e = c0; e < c1; e++) {
            if (tb[e]) treeL[tpos++] = (ushort)e;
            else       dualR[(ND - 1) - dpos++] = (ushort)e;
        }
        __syncthreads();
        if (tid == 0) { treeL[NT] = 0; dualR[ND] = 0; }
    }

    // ---- init packed UF arrays (pk1 region free now) ----
    for (int v = tid; v < N_V; v += 512)
        pk0[v] = ((u64)v << 48) | ((u64)(unsigned)g_rank[v] << 32)
               | (u64)__float_as_uint(img[v]);
    for (int t = tid; t < N_F; t += 512)
        pk1[t] = ((u64)t << 48) | ((u64)(unsigned)g_rank[N_V + N_E + t] << 32)
               | (u64)__float_as_uint(g_vals[N_V + N_E + t]);
    if (tid == 0)
        pk1[N_F] = ((u64)N_F << 48) | ((u64)(unsigned)M_S << 32);

    // ---- essential H0 (row 0): [min, max] over vertex values ----
    {
        float inf = __int_as_float(0x7f800000);
        float lmin = inf, lmax = -inf;
        for (int i = tid; i < N_V; i += 512) {
            float x = img[i];
            lmin = fminf(lmin, x); lmax = fmaxf(lmax, x);
        }
        s_min[tid] = lmin; s_max[tid] = lmax;
        __syncthreads();
        for (int st = 256; st > 0; st >>= 1) {
            if (tid < st) {
                s_min[tid] = fminf(s_min[tid], s_min[tid + st]);
                s_max[tid] = fmaxf(s_max[tid], s_max[tid + st]);
            }
            __syncthreads();
        }
        if (tid == 0) { out[0] = s_min[0]; out[1] = s_max[0]; }
    }
    __syncthreads();   // last block-wide barrier

    if (tid == 0) {
        // ================= dim 0: tree edges, increasing order =================
        float2* o0 = (float2*)out;
        int lastIdx = -1; u64 lastW = 0;
        int i = treeL[0];
        uint4 rc = rec[i];
        int u = (int)(rc.x & 0xffffu), v = (int)(rc.x >> 16);
        u64 wu = pk0[u], wv = pk0[v];
        for (int j = 0; j < NT; j++) {
            // prefetch next (sentinel at treeL[NT])
            int i2 = treeL[j + 1];
            uint4 rn = rec[i2];
            int un = (int)(rn.x & 0xffffu), vn = (int)(rn.x >> 16);
            u64 wun = pk0[un], wvn = pk0[vn];
            // patch against previous union write
            if (u == lastIdx) wu = lastW;
            if (v == lastIdx) wv = lastW;
            // 0/1-hop fast path (wpu/wpv are fresh reads)
            int pu = (int)(wu >> 48), pv = (int)(wv >> 48);
            u64 wpu = pk0[pu], wpv = pk0[pv];
            bool fu = (pu == u), fv = (pv == v);
            int ppu = (int)(wpu >> 48), ppv = (int)(wpv >> 48);
            int ru, rv; u64 wru, wrv;
            if (((!fu) & (ppu != pu)) | ((!fv) & (ppv != pv))) {
                wru = pfind(pk0, u, wu, ru);
                wrv = pfind(pk0, v, wv, rv);
            } else {
                ru = fu ? u : pu;  wru = fu ? wu : wpu;
                rv = fv ? v : pv;  wrv = fv ? wv : wpv;
            }
            // compress endpoints directly to their roots (idempotent at roots)
            pk0[u] = (wu & LOW48) | ((u64)ru << 48);
            pk0[v] = (wv & LOW48) | ((u64)rv << 48);
            // union (guaranteed: tree edge)
            int bu = (int)((wru >> 32) & 0xffffu);
            int bv = (int)((wrv >> 32) & 0xffffu);
            bool uy = (bu > bv);
            int y     = uy ? ru : rv;
            u64 wy    = uy ? wru : wrv;
            int row   = uy ? bu : bv;
            int elder = uy ? rv : ru;
            o0[row] = make_float2(__uint_as_float((unsigned)(wy & 0xffffffffu)),
                                  __uint_as_float(rc.y));
            u64 nw = (wy & LOW48) | ((u64)elder << 48);
            pk0[y] = nw;
            lastIdx = y; lastW = nw;
            rc = rn; u = un; v = vn; wu = wun; wv = wvn;
        }
    } else if (tid == 32) {
        // ========== dim 1: non-tree edges, decreasing order (dual UF) ==========
        float2* o1 = (float2*)(out + (size_t)2 * M_S);
        int lastIdx = -1; u64 lastW = 0;
        int i = dualR[0];
        uint4 rc = rec[i];
        int c0 = (int)(rc.w & 0xffffu), c1 = (int)(rc.w >> 16);
        int a = c0, b = (c1 == c0) ? N_F : c1;
        u64 wa = pk1[a], wb = pk1[b];
        for (int j = 0; j < ND; j++) {
            int i2 = dualR[j + 1];
            uint4 rn = rec[i2];
            int d0 = (int)(rn.w & 0xffffu), d1 = (int)(rn.w >> 16);
            int an = d0, bn = (d1 == d0) ? N_F : d1;
            u64 wan = pk1[an], wbn = pk1[bn];
            if (a == lastIdx) wa = lastW;
            if (b == lastIdx) wb = lastW;
            int pa = (int)(wa >> 48), pb = (int)(wb >> 48);
            u64 wpa = pk1[pa], wpb = pk1[pb];
            bool fa = (pa == a), fb = (pb == b);
            int ppa = (int)(wpa >> 48), ppb = (int)(wpb >> 48);
            int ra, rb; u64 wra, wrb;
            if (((!fa) & (ppa != pa)) | ((!fb) & (ppb != pb))) {
                wra = pfind(pk1, a, wa, ra);
                wrb = pfind(pk1, b, wb, rb);
            } else {
                ra = fa ? a : pa;  wra = fa ? wa : wpa;
                rb = fb ? b : pb;  wrb = fb ? wb : wpb;
            }
            pk1[a] = (wa & LOW48) | ((u64)ra << 48);
            pk1[b] = (wb & LOW48) | ((u64)rb << 48);
            // union (guaranteed: dual tree edge); dying = smaller forward rank
            int ba = (int)((wra >> 32) & 0xffffu);
            int bb = (int)((wrb >> 32) & 0xffffu);
            bool ad = (ba < bb);               // a-side dies
            int y    = ad ? ra : rb;
            u64 wy   = ad ? wra : wrb;
            int surv = ad ? rb : ra;
            int row  = (int)rc.z;
            o1[row] = make_float2(__uint_as_float(rc.y),
                                  __uint_as_float((unsigned)(wy & 0xffffffffu)));
            u64 nw = (wy & LOW48) | ((u64)surv << 48);
            pk1[y] = nw;
            lastIdx = y; lastW = nw;
            rc = rn; a = an; b = bn; wa = wan; wb = wbn;
        }
    }
    // all other threads exit
}

// ---------------------------------------------------------------------------
extern "C" void kernel_launch(void* const* d_in, const int* in_sizes, int n_in,
                              void* d_out, int out_size)
{
    const float* img   = (const float*)d_in[0];
    const int*   edges = (const int*)d_in[1];
    const int*   tris  = (const int*)d_in[2];
    float*       out   = (float*)d_out;

    cudaFuncSetAttribute(k_pair, cudaFuncAttributeMaxDynamicSharedMemorySize, SMEM_BYTES);

    k_vals<<<(M_S + 255) / 256, 256>>>(img, edges, tris, out, out_size);
    k_cof <<<(N_F + 255) / 256, 256>>>(tris);
    k_rank<<<(M_S + 255) / 256, 256>>>(edges);
    k_pair<<<1, 512, SMEM_BYTES>>>(img, out);
}

// round 6
// speedup vs baseline: 10.7111x; 1.0935x over previous
#include <cuda_runtime.h>
#include <stdint.h>

// Problem constants (fixed-shape problem: 48x48 grid, regular triangulation)
static constexpr int HH   = 48;
static constexpr int WW   = 48;
static constexpr int N_V  = HH * WW;                                          // 2304
static constexpr int N_E  = HH*(WW-1) + (HH-1)*WW + (HH-1)*(WW-1);            // 6721
static constexpr int N_F  = 2*(HH-1)*(WW-1);                                  // 4418
static constexpr int M_S  = N_V + N_E + N_F;                                  // 13443
static constexpr int NT   = N_V - 1;                                          // 2303 MST edges
static constexpr int ND   = N_E - NT;                                         // 4418 dual-tree edges

typedef unsigned long long u64;
static constexpr u64 LOW48 = 0x0000FFFFFFFFFFFFULL;

// Global scratch (no allocations allowed)
__device__ float g_vals[M_S];
__device__ u64   g_keys[M_S];
__device__ int   g_rank[M_S];
__device__ int   g_cof0[N_E];
__device__ int   g_cof1[N_E];
__device__ uint4 g_erec[N_E];   // sorted edge records

// Order-preserving map float -> uint32
__device__ __forceinline__ unsigned int fsort(float x) {
    unsigned int u = __float_as_uint(x);
    return (u & 0x80000000u) ? ~u : (u | 0x80000000u);
}

// ---------------------------------------------------------------------------
// K1: per-simplex filtration values + sort keys; init coface arrays; zero out
// ---------------------------------------------------------------------------
__global__ void k_vals(const float* __restrict__ img,
                       const int*   __restrict__ edges,
                       const int*   __restrict__ tris,
                       float* __restrict__ out, int out_n)
{
    int s   = blockIdx.x * blockDim.x + threadIdx.x;
    int gsz = gridDim.x * blockDim.x;
    for (int o = s; o < out_n; o += gsz) out[o] = 0.0f;   // clear poisoned output
    if (s >= M_S) return;

    float v;
    if (s < N_V) {
        v = img[s];
    } else if (s < N_V + N_E) {
        int e = s - N_V;
        v = fmaxf(img[edges[2*e]], img[edges[2*e + 1]]);
        g_cof0[e] = 0x7fffffff;
        g_cof1[e] = -1;
    } else {
        int t = s - N_V - N_E;
        float mx = -__int_as_float(0x7f800000);
        #pragma unroll
        for (int k = 0; k < 3; k++) {
            int e = tris[3*t + k];
            mx = fmaxf(mx, fmaxf(img[edges[2*e]], img[edges[2*e + 1]]));
        }
        v = mx;
    }
    g_vals[s] = v;
    // key = (sortable value, original index); dim is monotone in index, so
    // this reproduces lexsort((dims, vals)) exactly.
    g_keys[s] = ((u64)fsort(v) << 32) | (unsigned int)s;
}

// ---------------------------------------------------------------------------
// K2: edge -> triangle coface map (deterministic atomicMin/Max)
// ---------------------------------------------------------------------------
__global__ void k_cof(const int* __restrict__ tris)
{
    int t = blockIdx.x * blockDim.x + threadIdx.x;
    if (t >= N_F) return;
    #pragma unroll
    for (int k = 0; k < 3; k++) {
        int e = tris[3*t + k];
        atomicMin(&g_cof0[e], t);
        atomicMax(&g_cof1[e], t);
    }
}

// ---------------------------------------------------------------------------
// K3: rank by counting over smem chunks (all keys distinct).
// ---------------------------------------------------------------------------
static constexpr int RCHUNK = 4096;

__global__ void k_rank(const int* __restrict__ edges)
{
    __shared__ u64 sk[RCHUNK];
    int  s   = blockIdx.x * blockDim.x + threadIdx.x;
    bool act = (s < M_S);
    u64 my = act ? g_keys[s] : 0ULL;

    int rank = 0, erank = 0;
    for (int cb = 0; cb < M_S; cb += RCHUNK) {
        int cnt = min(RCHUNK, M_S - cb);
        __syncthreads();
        for (int j = threadIdx.x; j < cnt; j += blockDim.x) sk[j] = g_keys[cb + j];
        __syncthreads();
        if (act) {
            int jLo = max(0, min(cnt, N_V - cb));
            int jHi = max(jLo, min(cnt, N_V + N_E - cb));
            int j = 0;
            #pragma unroll 4
            for (; j < jLo; j++) rank += (sk[j] < my);
            #pragma unroll 4
            for (; j < jHi; j++) { bool lt = sk[j] < my; rank += lt; erank += lt; }
            #pragma unroll 4
            for (; j < cnt; j++) rank += (sk[j] < my);
        }
    }
    if (!act) return;
    g_rank[s] = rank;

    if (s >= N_V && s < N_V + N_E) {
        int e  = s - N_V;
        int u  = edges[2*e], v = edges[2*e + 1];
        int c0 = g_cof0[e],  c1 = g_cof1[e];
        uint4 r;
        r.x = (unsigned)u | ((unsigned)v << 16);   // endpoints (< 2304, 16b each)
        r.y = __float_as_uint(g_vals[s]);          // edge value
        r.z = (unsigned)rank;                      // global rank of this edge
        r.w = (unsigned)c0 | ((unsigned)c1 << 16); // cofaces; c0==c1 => boundary
        g_erec[erank] = r;
    }
}

// ---------------------------------------------------------------------------
// K4: single block, 512 threads.
// Phase A (parallel): stage rec; Borůvka MST (weights = sorted edge index).
// Phase B (parallel): order-preserving compaction to treeL (inc) / dualR (dec);
//   init packed UF arrays; min/max reduction.
// Phase C (serial x2, concurrent warps, 3-stage software pipeline):
//   tid 0 = dim0 over treeL, tid 32 = dim1 over dualR (every edge a union).
// Node word: [parent:16 | birth-rank:16 | birth-val:32]; root <=> parent==self.
// ---------------------------------------------------------------------------
static constexpr int SMEM_BYTES =
      N_E*16            // rec
    + N_V*8             // pk0
    + 4420*8            // pk1
    + N_V*4             // par
    + N_V*4             // best
    + (NT+2)*2          // treeL + 2 sentinels
    + (ND+2)*2          // dualR + 2 sentinels
    + N_E               // tb
    + 64;               // slack

// full find with path halving; w = starting word for x (parent may be stale
// but always an ancestor)
__device__ __forceinline__ u64 pfind(u64* __restrict__ pk, int x, u64 w, int& root)
{
    for (;;) {
        int par = (int)(w >> 48);
        if (par == x) { root = x; return w; }
        u64 wp = pk[par];
        int gp = (int)(wp >> 48);
        if (gp != par) pk[x] = (w & LOW48) | ((u64)gp << 48);  // halve
        x = par; w = wp;
    }
}

__global__ void __launch_bounds__(512, 1)
k_pair(const float* __restrict__ img, float* __restrict__ out)
{
    extern __shared__ uint4 smq[];
    uint4*  rec   = smq;                                  // [N_E]
    u64*    pk0   = (u64*)(rec + N_E);                    // [N_V]
    u64*    pk1   = pk0 + N_V;                            // [4420]
    int*    par   = (int*)(pk1 + 4420);                   // [N_V]
    int*    best  = par + N_V;                            // [N_V]
    ushort* treeL = (ushort*)(best + N_V);                // [NT+2]
    ushort* dualR = treeL + (NT + 2);                     // [ND+2]
    unsigned char* tb = (unsigned char*)(dualR + (ND + 2)); // [N_E]
    int*    par2  = (int*)pk1;   // snapshot buffer, reused before pk1 init

    __shared__ float s_min[512], s_max[512];
    __shared__ int   s_scan[512];
    __shared__ int   s_changed;

    int tid = threadIdx.x;

    // ---- stage records, init Borůvka state ----
    for (int i = tid; i < N_E; i += 512) { rec[i] = g_erec[i]; tb[i] = 0; }
    for (int v = tid; v < N_V; v += 512) par[v] = v;
    __syncthreads();

    // ---- Borůvka MST (weight = sorted edge index, all distinct) ----
    for (int round = 0; round < 20; round++) {
        if (tid == 0) s_changed = 0;
        for (int v = tid; v < N_V; v += 512) best[v] = 0x7fffffff;
        __syncthreads();
        for (int e = tid; e < N_E; e += 512) {
            unsigned ex = rec[e].x;
            int ru = par[(int)(ex & 0xffffu)];
            int rv = par[(int)(ex >> 16)];
            if (ru != rv) { atomicMin(&best[ru], e); atomicMin(&best[rv], e); }
        }
        for (int v = tid; v < N_V; v += 512) par2[v] = par[v];
        __syncthreads();
        for (int v = tid; v < N_V; v += 512) {
            if (par2[v] == v) {
                int e = best[v];
                if (e != 0x7fffffff) {
                    unsigned ex = rec[e].x;
                    int ra = par2[(int)(ex & 0xffffu)];
                    int rb = par2[(int)(ex >> 16)];
                    int other = (ra == v) ? rb : ra;
                    bool mutual = (best[other] == e);
                    if (!mutual || v > other) {
                        par[v] = other;
                        tb[e]  = 1;
                        s_changed = 1;
                    }
                }
            }
        }
        __syncthreads();
        for (int v = tid; v < N_V; v += 512) {
            int r = par[v], pr = par[r];
            while (pr != r) { r = pr; pr = par[r]; }
            par[v] = r;
        }
        __syncthreads();
        if (!s_changed) break;
    }

    // ---- order-preserving compaction: tree -> treeL (inc), non-tree -> dualR (dec) ----
    {
        const int CH = 14;                       // 512*14 = 7168 >= N_E
        int c0 = tid * CH;
        int c1 = min(N_E, c0 + CH);
        if (c0 > N_E) c0 = N_E;
        int cnt = 0;
        for (int e = c0; e < c1; e++) cnt += tb[e];
        s_scan[tid] = cnt;
        __syncthreads();
        for (int off = 1; off < 512; off <<= 1) {
            int x = s_scan[tid];
            int y = (tid >= off) ? s_scan[tid - off] : 0;
            __syncthreads();
            s_scan[tid] = x + y;
            __syncthreads();
        }
        int excl = s_scan[tid] - cnt;
        int tpos = excl;
        int dpos = c0 - excl;
        for (int e = c0; e < c1; e++) {
            if (tb[e]) treeL[tpos++] = (ushort)e;
            else       dualR[(ND - 1) - dpos++] = (ushort)e;
        }
        __syncthreads();
        if (tid == 0) {
            treeL[NT] = 0; treeL[NT + 1] = 0;
            dualR[ND] = 0; dualR[ND + 1] = 0;
        }
    }

    // ---- init packed UF arrays (pk1 region free now) ----
    for (int v = tid; v < N_V; v += 512)
        pk0[v] = ((u64)v << 48) | ((u64)(unsigned)g_rank[v] << 32)
               | (u64)__float_as_uint(img[v]);
    for (int t = tid; t < N_F; t += 512)
        pk1[t] = ((u64)t << 48) | ((u64)(unsigned)g_rank[N_V + N_E + t] << 32)
               | (u64)__float_as_uint(g_vals[N_V + N_E + t]);
    if (tid == 0)
        pk1[N_F] = ((u64)N_F << 48) | ((u64)(unsigned)M_S << 32);

    // ---- essential H0 (row 0): [min, max] over vertex values ----
    {
        float inf = __int_as_float(0x7f800000);
        float lmin = inf, lmax = -inf;
        for (int i = tid; i < N_V; i += 512) {
            float x = img[i];
            lmin = fminf(lmin, x); lmax = fmaxf(lmax, x);
        }
        s_min[tid] = lmin; s_max[tid] = lmax;
        __syncthreads();
        for (int st = 256; st > 0; st >>= 1) {
            if (tid < st) {
                s_min[tid] = fminf(s_min[tid], s_min[tid + st]);
                s_max[tid] = fmaxf(s_max[tid], s_max[tid + st]);
            }
            __syncthreads();
        }
        if (tid == 0) { out[0] = s_min[0]; out[1] = s_max[0]; }
    }
    __syncthreads();   // last block-wide barrier

    if (tid == 0) {
        // ================= dim 0: tree edges, increasing order =================
        float2* o0 = (float2*)out;
        int lastIdx = -1; u64 lastW = 0;
        // pipeline prologue: stage j=0 fully, index for j=1
        int iA = treeL[0];
        uint4 rA = rec[iA];
        int u = (int)(rA.x & 0xffffu), v = (int)(rA.x >> 16);
        unsigned val = rA.y;
        u64 wu = pk0[u], wv = pk0[v];
        int iB = treeL[1];
        for (int j = 0; j < NT; j++) {
            // prefetch: index for j+2, record + UF words for j+1
            int iC = treeL[j + 2];
            uint4 rB = rec[iB];
            int un = (int)(rB.x & 0xffffu), vn = (int)(rB.x >> 16);
            unsigned valn = rB.y;
            u64 wun = pk0[un], wvn = pk0[vn];
            // ---- process j ----
            if (u == lastIdx) wu = lastW;
            if (v == lastIdx) wv = lastW;
            int pu = (int)(wu >> 48), pv = (int)(wv >> 48);
            u64 wpu = pk0[pu], wpv = pk0[pv];
            bool fu = (pu == u), fv = (pv == v);
            int ppu = (int)(wpu >> 48), ppv = (int)(wpv >> 48);
            int ru, rv; u64 wru, wrv;
            if (__builtin_expect((int)((((!fu) & (ppu != pu)) | ((!fv) & (ppv != pv)))), 0)) {
                wru = pfind(pk0, u, wu, ru);
                wrv = pfind(pk0, v, wv, rv);
            } else {
                ru = fu ? u : pu;  wru = fu ? wu : wpu;
                rv = fv ? v : pv;  wrv = fv ? wv : wpv;
            }
            // compress endpoints to roots (idempotent at roots)
            pk0[u] = (wu & LOW48) | ((u64)ru << 48);
            pk0[v] = (wv & LOW48) | ((u64)rv << 48);
            // union (guaranteed: tree edge)
            int bu = (int)((wru >> 32) & 0xffffu);
            int bv = (int)((wrv >> 32) & 0xffffu);
            bool uy = (bu > bv);
            int y     = uy ? ru : rv;
            u64 wy    = uy ? wru : wrv;
            int row   = uy ? bu : bv;
            int elder = uy ? rv : ru;
            o0[row] = make_float2(__uint_as_float((unsigned)(wy & 0xffffffffu)),
                                  __uint_as_float(val));
            u64 nw = (wy & LOW48) | ((u64)elder << 48);
            pk0[y] = nw;
            lastIdx = y; lastW = nw;
            // shift pipeline
            iB = iC; u = un; v = vn; wu = wun; wv = wvn; val = valn;
        }
    } else if (tid == 32) {
        // ========== dim 1: non-tree edges, decreasing order (dual UF) ==========
        float2* o1 = (float2*)(out + (size_t)2 * M_S);
        int lastIdx = -1; u64 lastW = 0;
        int iA = dualR[0];
        uint4 rA = rec[iA];
        int c0 = (int)(rA.w & 0xffffu), c1 = (int)(rA.w >> 16);
        int a = c0, b = (c1 == c0) ? N_F : c1;
        unsigned val = rA.y; int row = (int)rA.z;
        u64 wa = pk1[a], wb = pk1[b];
        int iB = dualR[1];
        for (int j = 0; j < ND; j++) {
            int iC = dualR[j + 2];
            uint4 rB = rec[iB];
            int d0 = (int)(rB.w & 0xffffu), d1 = (int)(rB.w >> 16);
            int an = d0, bn = (d1 == d0) ? N_F : d1;
            unsigned valn = rB.y; int rown = (int)rB.z;
            u64 wan = pk1[an], wbn = pk1[bn];
            // ---- process j ----
            if (a == lastIdx) wa = lastW;
            if (b == lastIdx) wb = lastW;
            int pa = (int)(wa >> 48), pb = (int)(wb >> 48);
            u64 wpa = pk1[pa], wpb = pk1[pb];
            bool fa = (pa == a), fb = (pb == b);
            int ppa = (int)(wpa >> 48), ppb = (int)(wpb >> 48);
            int ra, rb; u64 wra, wrb;
            if (__builtin_expect((int)((((!fa) & (ppa != pa)) | ((!fb) & (ppb != pb)))), 0)) {
                wra = pfind(pk1, a, wa, ra);
                wrb = pfind(pk1, b, wb, rb);
            } else {
                ra = fa ? a : pa;  wra = fa ? wa : wpa;
                rb = fb ? b : pb;  wrb = fb ? wb : wpb;
            }
            pk1[a] = (wa & LOW48) | ((u64)ra << 48);
            pk1[b] = (wb & LOW48) | ((u64)rb << 48);
            // union (guaranteed: dual tree edge); dying = smaller forward rank
            int ba = (int)((wra >> 32) & 0xffffu);
            int bb = (int)((wrb >> 32) & 0xffffu);
            bool ad = (ba < bb);               // a-side dies
            int y    = ad ? ra : rb;
            u64 wy   = ad ? wra : wrb;
            int surv = ad ? rb : ra;
            o1[row] = make_float2(__uint_as_float(val),
                                  __uint_as_float((unsigned)(wy & 0xffffffffu)));
            u64 nw = (wy & LOW48) | ((u64)surv << 48);
            pk1[y] = nw;
            lastIdx = y; lastW = nw;
            iB = iC; a = an; b = bn; wa = wan; wb = wbn; val = valn; row = rown;
        }
    }
    // all other threads exit
}

// ---------------------------------------------------------------------------
extern "C" void kernel_launch(void* const* d_in, const int* in_sizes, int n_in,
                              void* d_out, int out_size)
{
    const float* img   = (const float*)d_in[0];
    const int*   edges = (const int*)d_in[1];
    const int*   tris  = (const int*)d_in[2];
    float*       out   = (float*)d_out;

    cudaFuncSetAttribute(k_pair, cudaFuncAttributeMaxDynamicSharedMemorySize, SMEM_BYTES);

    k_vals<<<(M_S + 255) / 256, 256>>>(img, edges, tris, out, out_size);
    k_cof <<<(N_F + 255) / 256, 256>>>(tris);
    k_rank<<<(M_S + 255) / 256, 256>>>(edges);
    k_pair<<<1, 512, SMEM_BYTES>>>(img, out);
}

// round 7
// speedup vs baseline: 18.8367x; 1.7586x over previous
#include <cuda_runtime.h>
#include <stdint.h>

// Problem constants (fixed-shape problem: 48x48 grid, regular triangulation)
static constexpr int HH   = 48;
static constexpr int WW   = 48;
static constexpr int N_V  = HH * WW;                                          // 2304
static constexpr int N_E  = HH*(WW-1) + (HH-1)*WW + (HH-1)*(WW-1);            // 6721
static constexpr int N_F  = 2*(HH-1)*(WW-1);                                  // 4418
static constexpr int M_S  = N_V + N_E + N_F;                                  // 13443
static constexpr int NT   = N_V - 1;                                          // 2303 MST edges
static constexpr int ND   = N_E - NT;                                         // 4418 dual-tree edges
static constexpr int N1   = N_F + 1;                                          // 4419 dual nodes

typedef unsigned long long u64;

// Global scratch (no allocations allowed)
__device__ float g_vals[M_S];
__device__ u64   g_keys[M_S];
__device__ int   g_rank[M_S];
__device__ float g_sval[M_S];   // value at sorted position
__device__ int   g_cof0[N_E];
__device__ int   g_cof1[N_E];
__device__ uint4 g_erec[N_E];   // sorted edge records

// Order-preserving map float -> uint32
__device__ __forceinline__ unsigned int fsort(float x) {
    unsigned int u = __float_as_uint(x);
    return (u & 0x80000000u) ? ~u : (u | 0x80000000u);
}

// ---------------------------------------------------------------------------
// K1: per-simplex filtration values + sort keys; init coface arrays; zero out
// ---------------------------------------------------------------------------
__global__ void k_vals(const float* __restrict__ img,
                       const int*   __restrict__ edges,
                       const int*   __restrict__ tris,
                       float* __restrict__ out, int out_n)
{
    int s   = blockIdx.x * blockDim.x + threadIdx.x;
    int gsz = gridDim.x * blockDim.x;
    for (int o = s; o < out_n; o += gsz) out[o] = 0.0f;   // clear poisoned output
    if (s >= M_S) return;

    float v;
    if (s < N_V) {
        v = img[s];
    } else if (s < N_V + N_E) {
        int e = s - N_V;
        v = fmaxf(img[edges[2*e]], img[edges[2*e + 1]]);
        g_cof0[e] = 0x7fffffff;
        g_cof1[e] = -1;
    } else {
        int t = s - N_V - N_E;
        float mx = -__int_as_float(0x7f800000);
        #pragma unroll
        for (int k = 0; k < 3; k++) {
            int e = tris[3*t + k];
            mx = fmaxf(mx, fmaxf(img[edges[2*e]], img[edges[2*e + 1]]));
        }
        v = mx;
    }
    g_vals[s] = v;
    // key = (sortable value, original index); dim is monotone in index, so
    // this reproduces lexsort((dims, vals)) exactly.
    g_keys[s] = ((u64)fsort(v) << 32) | (unsigned int)s;
}

// ---------------------------------------------------------------------------
// K2: edge -> triangle coface map (deterministic atomicMin/Max)
// ---------------------------------------------------------------------------
__global__ void k_cof(const int* __restrict__ tris)
{
    int t = blockIdx.x * blockDim.x + threadIdx.x;
    if (t >= N_F) return;
    #pragma unroll
    for (int k = 0; k < 3; k++) {
        int e = tris[3*t + k];
        atomicMin(&g_cof0[e], t);
        atomicMax(&g_cof1[e], t);
    }
}

// ---------------------------------------------------------------------------
// K3: rank by counting over smem chunks (all keys distinct). Also builds the
// rank->value table and writes the essential-H0 row (out[0..1]).
// ---------------------------------------------------------------------------
static constexpr int RCHUNK = 4096;

__global__ void k_rank(const int* __restrict__ edges, float* __restrict__ out)
{
    __shared__ u64 sk[RCHUNK];
    int  s   = blockIdx.x * blockDim.x + threadIdx.x;
    bool act = (s < M_S);
    u64 my = act ? g_keys[s] : 0ULL;

    int rank = 0, erank = 0;
    for (int cb = 0; cb < M_S; cb += RCHUNK) {
        int cnt = min(RCHUNK, M_S - cb);
        __syncthreads();
        for (int j = threadIdx.x; j < cnt; j += blockDim.x) sk[j] = g_keys[cb + j];
        __syncthreads();
        if (act) {
            int jLo = max(0, min(cnt, N_V - cb));
            int jHi = max(jLo, min(cnt, N_V + N_E - cb));
            int j = 0;
            #pragma unroll 4
            for (; j < jLo; j++) rank += (sk[j] < my);
            #pragma unroll 4
            for (; j < jHi; j++) { bool lt = sk[j] < my; rank += lt; erank += lt; }
            #pragma unroll 4
            for (; j < cnt; j++) rank += (sk[j] < my);
        }
    }
    if (!act) return;
    g_rank[s] = rank;
    float myval = g_vals[s];
    g_sval[rank] = myval;
    if (rank == 0)       out[0] = myval;   // essential H0 birth (global min vertex)
    if (rank == M_S - 1) out[1] = myval;   // its death = fmax

    if (s >= N_V && s < N_V + N_E) {
        int e  = s - N_V;
        int u  = edges[2*e], v = edges[2*e + 1];
        int c0 = g_cof0[e],  c1 = g_cof1[e];
        uint4 r;
        r.x = (unsigned)u | ((unsigned)v << 16);   // endpoints
        r.y = __float_as_uint(myval);              // edge value
        r.z = (unsigned)rank;                      // global rank of this edge
        r.w = (unsigned)c0 | ((unsigned)c1 << 16); // cofaces; c0==c1 => boundary
        g_erec[erank] = r;
    }
}

// ---------------------------------------------------------------------------
// K4: single block, 512 threads.
//  A) stage edges; Borůvka MST (weights = sorted edge index) -> tb[]
//  B) order-preserving compaction -> treeL (inc) / dualR (dec)
//  C) staged parallel CC to build per-segment UF snapshots at cuts
//     (node word u32 = [root:16 | comp birth rank:16], fully compressed)
//  D) 8 concurrent serial UF threads (4 segments x 2 dims); emit dying rank
//  E) parallel epilogue: resolve values via g_sval/g_erec, write diagram rows
// ---------------------------------------------------------------------------
// smem layout (bytes)
static constexpr int OFF_EX    = 0;                        // u32[N_E]   26884
static constexpr int OFF_EW    = 26884;                    // u32[N_E]   26884
static constexpr int OFF_TREE  = 53768;                    // u16[NT+2]   4610
static constexpr int OFF_DUAL  = 58378;                    // u16[ND+2]   8840
static constexpr int OFF_LAB   = 67220;                    // u32[N1]    17676
static constexpr int OFF_RKM   = 84896;                    // u32[N1]    17676
static constexpr int OFF_SEG0  = 102572;                   // u32[4*N_V] 36864
static constexpr int OFF_SEG1  = 139436;                   // u32[4*N1]  70704
static constexpr int OFF_DR0   = 210140;                   // u16[2304]   4608
static constexpr int OFF_DR1   = 214748;                   // u16[4420]   8840
static constexpr int SMEM_BYTES= 223588;
// Borůvka overlays (inside SEG1 region, dead before SEG1 is written)
static constexpr int OFF_PAR   = OFF_SEG1;                 // int[N_V]
static constexpr int OFF_BEST  = OFF_SEG1 + 9216;          // int[N_V]
static constexpr int OFF_PAR2  = OFF_SEG1 + 18432;         // int[N_V]
static constexpr int OFF_TB    = OFF_SEG1 + 27648;         // u8[N_E]

__device__ static const int CUT0[5] = {0, 575, 1151, 1727, NT};
__device__ static const int CUT1[5] = {0, 1104, 2209, 3313, ND};

__device__ __forceinline__ int chase32(unsigned* L, int x) {
    int p = (int)L[x];
    while (p != x) { x = p; p = (int)L[x]; }
    return x;
}

// serial find with path halving on u32 packed words
__device__ __forceinline__ unsigned sfind(unsigned* __restrict__ sg, int x,
                                          unsigned w, int& root)
{
    for (;;) {
        int p = (int)(w >> 16);
        if (p == x) { root = x; return w; }
        unsigned wp = sg[p];
        int gp = (int)(wp >> 16);
        if (gp != p) sg[x] = (w & 0xffffu) | ((unsigned)gp << 16);
        x = p; w = wp;
    }
}

__global__ void __launch_bounds__(512, 1)
k_pair(const float* __restrict__ img, float* __restrict__ out)
{
    extern __shared__ char smb[];
    unsigned* ex     = (unsigned*)(smb + OFF_EX);
    unsigned* ew     = (unsigned*)(smb + OFF_EW);
    ushort*   treeL  = (ushort*)(smb + OFF_TREE);
    ushort*   dualR  = (ushort*)(smb + OFF_DUAL);
    unsigned* lab    = (unsigned*)(smb + OFF_LAB);
    unsigned* rkm    = (unsigned*)(smb + OFF_RKM);
    unsigned* seg0   = (unsigned*)(smb + OFF_SEG0);
    unsigned* seg1   = (unsigned*)(smb + OFF_SEG1);
    ushort*   drank0 = (ushort*)(smb + OFF_DR0);
    ushort*   drank1 = (ushort*)(smb + OFF_DR1);
    int*      par    = (int*)(smb + OFF_PAR);
    int*      best   = (int*)(smb + OFF_BEST);
    int*      par2   = (int*)(smb + OFF_PAR2);
    unsigned char* tb = (unsigned char*)(smb + OFF_TB);

    __shared__ int s_scan[512];
    __shared__ int s_changed;

    int tid = threadIdx.x;

    // ---- A: stage edges, init Borůvka ----
    for (int e = tid; e < N_E; e += 512) {
        uint4 r = g_erec[e];
        ex[e] = r.x;
        unsigned c0 = r.w & 0xffffu, c1 = r.w >> 16;
        unsigned b  = (c1 == c0) ? (unsigned)N_F : c1;
        ew[e] = c0 | (b << 16);
        tb[e] = 0;
    }
    for (int v = tid; v < N_V; v += 512) par[v] = v;
    __syncthreads();

    // ---- Borůvka MST (weight = sorted edge index, all distinct) ----
    for (int round = 0; round < 20; round++) {
        if (tid == 0) s_changed = 0;
        for (int v = tid; v < N_V; v += 512) best[v] = 0x7fffffff;
        __syncthreads();
        for (int e = tid; e < N_E; e += 512) {
            unsigned x = ex[e];
            int ru = par[(int)(x & 0xffffu)];
            int rv = par[(int)(x >> 16)];
            if (ru != rv) { atomicMin(&best[ru], e); atomicMin(&best[rv], e); }
        }
        for (int v = tid; v < N_V; v += 512) par2[v] = par[v];
        __syncthreads();
        for (int v = tid; v < N_V; v += 512) {
            if (par2[v] == v) {
                int e = best[v];
                if (e != 0x7fffffff) {
                    unsigned x = ex[e];
                    int ra = par2[(int)(x & 0xffffu)];
                    int rb = par2[(int)(x >> 16)];
                    int other = (ra == v) ? rb : ra;
                    bool mutual = (best[other] == e);
                    if (!mutual || v > other) {
                        par[v] = other;
                        tb[e]  = 1;
                        s_changed = 1;
                    }
                }
            }
        }
        __syncthreads();
        for (int v = tid; v < N_V; v += 512) {
            int r = par[v], pr = par[r];
            while (pr != r) { r = pr; pr = par[r]; }
            par[v] = r;
        }
        __syncthreads();
        if (!s_changed) break;
    }

    // ---- B: order-preserving compaction ----
    {
        const int CH = 14;                       // 512*14 = 7168 >= N_E
        int c0 = min(N_E, tid * CH);
        int c1 = min(N_E, c0 + CH);
        int cnt = 0;
        for (int e = c0; e < c1; e++) cnt += tb[e];
        s_scan[tid] = cnt;
        __syncthreads();
        for (int off = 1; off < 512; off <<= 1) {
            int x = s_scan[tid];
            int y = (tid >= off) ? s_scan[tid - off] : 0;
            __syncthreads();
            s_scan[tid] = x + y;
            __syncthreads();
        }
        int excl = s_scan[tid] - cnt;
        int tpos = excl;
        int dpos = c0 - excl;
        for (int e = c0; e < c1; e++) {
            if (tb[e]) treeL[tpos++] = (ushort)e;
            else       dualR[(ND - 1) - dpos++] = (ushort)e;
        }
        __syncthreads();
        if (tid == 0) {
            treeL[NT] = 0; treeL[NT + 1] = 0;
            dualR[ND] = 0; dualR[ND + 1] = 0;
        }
        __syncthreads();
    }

    // ---- C1: dim0 staged CC + segment snapshots ----
    for (int v = tid; v < N_V; v += 512) {
        unsigned rk = (unsigned)g_rank[v];
        lab[v]  = (unsigned)v;
        seg0[v] = ((unsigned)v << 16) | rk;       // snapshot p=0 (identity)
    }
    __syncthreads();
    for (int p = 1; p < 4; p++) {
        for (int round = 0; round < 24; round++) {
            if (tid == 0) s_changed = 0;
            __syncthreads();
            for (int j = CUT0[p-1] + tid; j < CUT0[p]; j += 512) {
                unsigned x = ex[treeL[j]];
                int ra = chase32(lab, (int)(x & 0xffffu));
                int rb = chase32(lab, (int)(x >> 16));
                if (ra != rb) {
                    int mn = min(ra, rb), mx = max(ra, rb);
                    atomicMin(&lab[mx], (unsigned)mn);
                    s_changed = 1;
                }
            }
            __syncthreads();
            for (int v = tid; v < N_V; v += 512) {
                int r = (int)lab[v], pr = (int)lab[r];
                while (pr != r) { r = pr; pr = (int)lab[r]; }
                lab[v] = (unsigned)r;
            }
            __syncthreads();
            if (!s_changed) break;
        }
        for (int v = tid; v < N_V; v += 512) rkm[v] = 0xffffffffu;
        __syncthreads();
        for (int v = tid; v < N_V; v += 512)
            atomicMin(&rkm[lab[v]], (unsigned)g_rank[v]);
        __syncthreads();
        unsigned* sg = seg0 + p * N_V;
        for (int v = tid; v < N_V; v += 512)
            sg[v] = (lab[v] << 16) | (rkm[lab[v]] & 0xffffu);
        __syncthreads();
    }

    // ---- C2: dim1 staged CC + segment snapshots (dual graph, MAX rank) ----
    for (int t = tid; t < N1; t += 512) {
        unsigned rk = (t < N_F) ? (unsigned)g_rank[N_V + N_E + t] : (unsigned)M_S;
        lab[t]  = (unsigned)t;
        seg1[t] = ((unsigned)t << 16) | rk;       // snapshot p=0 (identity)
    }
    __syncthreads();
    for (int p = 1; p < 4; p++) {
        for (int round = 0; round < 24; round++) {
            if (tid == 0) s_changed = 0;
            __syncthreads();
            for (int j = CUT1[p-1] + tid; j < CUT1[p]; j += 512) {
                unsigned x = ew[dualR[j]];
                int ra = chase32(lab, (int)(x & 0xffffu));
                int rb = chase32(lab, (int)(x >> 16));
                if (ra != rb) {
                    int mn = min(ra, rb), mx = max(ra, rb);
                    atomicMin(&lab[mx], (unsigned)mn);
                    s_changed = 1;
                }
            }
            __syncthreads();
            for (int t = tid; t < N1; t += 512) {
                int r = (int)lab[t], pr = (int)lab[r];
                while (pr != r) { r = pr; pr = (int)lab[r]; }
                lab[t] = (unsigned)r;
            }
            __syncthreads();
            if (!s_changed) break;
        }
        for (int t = tid; t < N1; t += 512) rkm[t] = 0u;
        __syncthreads();
        for (int t = tid; t < N1; t += 512) {
            unsigned rk = (t < N_F) ? (unsigned)g_rank[N_V + N_E + t] : (unsigned)M_S;
            atomicMax(&rkm[lab[t]], rk);
        }
        __syncthreads();
        unsigned* sg = seg1 + p * N1;
        for (int t = tid; t < N1; t += 512)
            sg[t] = (lab[t] << 16) | (rkm[lab[t]] & 0xffffu);
        __syncthreads();
    }

    // ---- D: 8 concurrent serial UF threads ----
    int wid = tid >> 5, lane = tid & 31;
    if (lane == 0 && wid < 4) {
        // dim0 segment wid: increasing order; dying = LARGER birth rank
        int p = wid;
        unsigned* sg = seg0 + p * N_V;
        int lo = CUT0[p], hi = CUT0[p + 1];
        int lastIdx = -1; unsigned lastW = 0;
        unsigned x = ex[treeL[lo]];
        int u = (int)(x & 0xffffu), v = (int)(x >> 16);
        unsigned wu = sg[u], wv = sg[v];
        for (int j = lo; j < hi; j++) {
            unsigned x2 = ex[treeL[j + 1]];
            int un = (int)(x2 & 0xffffu), vn = (int)(x2 >> 16);
            unsigned wun = sg[un], wvn = sg[vn];
            if (u == lastIdx) wu = lastW;
            if (v == lastIdx) wv = lastW;
            int pu = (int)(wu >> 16), pv = (int)(wv >> 16);
            unsigned wpu = sg[pu], wpv = sg[pv];
            bool fu = (pu == u), fv = (pv == v);
            int ru, rv; unsigned wru, wrv;
            if (__builtin_expect((int)(((!fu) & ((int)(wpu >> 16) != pu)) |
                                       ((!fv) & ((int)(wpv >> 16) != pv))), 0)) {
                wru = sfind(sg, u, wu, ru);
                wrv = sfind(sg, v, wv, rv);
            } else {
                ru = fu ? u : pu;  wru = fu ? wu : wpu;
                rv = fv ? v : pv;  wrv = fv ? wv : wpv;
            }
            sg[u] = ((unsigned)ru << 16) | (wru & 0xffffu);
            sg[v] = ((unsigned)rv << 16) | (wrv & 0xffffu);
            int bu = (int)(wru & 0xffffu), bv = (int)(wrv & 0xffffu);
            bool uy = (bu > bv);
            int y = uy ? ru : rv;
            unsigned wsur = uy ? wrv : wru;
            drank0[j] = (ushort)(uy ? bu : bv);
            sg[y] = wsur;
            lastIdx = y; lastW = wsur;
            u = un; v = vn; wu = wun; wv = wvn;
        }
    } else if (lane == 0 && wid < 8) {
        // dim1 segment wid-4: decreasing order; dying = SMALLER forward rank
        int p = wid - 4;
        unsigned* sg = seg1 + p * N1;
        int lo = CUT1[p], hi = CUT1[p + 1];
        int lastIdx = -1; unsigned lastW = 0;
        unsigned x = ew[dualR[lo]];
        int a = (int)(x & 0xffffu), b = (int)(x >> 16);
        unsigned wa = sg[a], wb = sg[b];
        for (int j = lo; j < hi; j++) {
            unsigned x2 = ew[dualR[j + 1]];
            int an = (int)(x2 & 0xffffu), bn = (int)(x2 >> 16);
            unsigned wan = sg[an], wbn = sg[bn];
            if (a == lastIdx) wa = lastW;
            if (b == lastIdx) wb = lastW;
            int pa = (int)(wa >> 16), pb = (int)(wb >> 16);
            unsigned wpa = sg[pa], wpb = sg[pb];
            bool fa = (pa == a), fb = (pb == b);
            int ra, rb; unsigned wra, wrb;
            if (__builtin_expect((int)(((!fa) & ((int)(wpa >> 16) != pa)) |
                                       ((!fb) & ((int)(wpb >> 16) != pb))), 0)) {
                wra = sfind(sg, a, wa, ra);
                wrb = sfind(sg, b, wb, rb);
            } else {
                ra = fa ? a : pa;  wra = fa ? wa : wpa;
                rb = fb ? b : pb;  wrb = fb ? wb : wpb;
            }
            sg[a] = ((unsigned)ra << 16) | (wra & 0xffffu);
            sg[b] = ((unsigned)rb << 16) | (wrb & 0xffffu);
            int ba = (int)(wra & 0xffffu), bb = (int)(wrb & 0xffffu);
            bool ad = (ba < bb);                  // a-side dies
            int y = ad ? ra : rb;
            unsigned wsur = ad ? wrb : wra;
            drank1[j] = (ushort)(ad ? ba : bb);
            sg[y] = wsur;
            lastIdx = y; lastW = wsur;
            a = an; b = bn; wa = wan; wb = wbn;
        }
    }
    __syncthreads();

    // ---- E: parallel epilogue (resolve values, write diagram rows) ----
    float2* o0 = (float2*)out;
    float2* o1 = o0 + M_S;
    for (int j = tid; j < NT; j += 512) {
        int row = drank0[j];
        int e   = treeL[j];
        float ev = __uint_as_float(g_erec[e].y);
        o0[row] = make_float2(g_sval[row], ev);        // (birth, death)
    }
    for (int j = tid; j < ND; j += 512) {
        int e = dualR[j];
        uint4 r = g_erec[e];
        int dr = drank1[j];
        o1[(int)r.z] = make_float2(__uint_as_float(r.y), g_sval[dr]);
    }
}

// ---------------------------------------------------------------------------
extern "C" void kernel_launch(void* const* d_in, const int* in_sizes, int n_in,
                              void* d_out, int out_size)
{
    const float* img   = (const float*)d_in[0];
    const int*   edges = (const int*)d_in[1];
    const int*   tris  = (const int*)d_in[2];
    float*       out   = (float*)d_out;

    cudaFuncSetAttribute(k_pair, cudaFuncAttributeMaxDynamicSharedMemorySize, SMEM_BYTES);

    k_vals<<<(M_S + 255) / 256, 256>>>(img, edges, tris, out, out_size);
    k_cof <<<(N_F + 255) / 256, 256>>>(tris);
    k_rank<<<(M_S + 255) / 256, 256>>>(edges, out);
    k_pair<<<1, 512, SMEM_BYTES>>>(img, out);
}

// round 8
// speedup vs baseline: 20.3273x; 1.0791x over previous
#include <cuda_runtime.h>
#include <stdint.h>

// Problem constants (fixed-shape problem: 48x48 grid, regular triangulation)
static constexpr int HH   = 48;
static constexpr int WW   = 48;
static constexpr int N_V  = HH * WW;                                          // 2304
static constexpr int N_E  = HH*(WW-1) + (HH-1)*WW + (HH-1)*(WW-1);            // 6721
static constexpr int N_F  = 2*(HH-1)*(WW-1);                                  // 4418
static constexpr int M_S  = N_V + N_E + N_F;                                  // 13443
static constexpr int N1   = N_F + 1;                                          // 4419 dual nodes

// analytic complex constants
static constexpr int A_NH = HH*(WW-1);        // 2256 horizontal edges
static constexpr int A_NV = (HH-1)*WW;        // 2256 vertical edges
static constexpr int TRI_A = (HH-1)*(WW-1);   // 2209 (# of A-triangles)

typedef unsigned long long u64;

// Global scratch (no allocations allowed)
__device__ float g_vals[M_S];
__device__ u64   g_keys[M_S];
__device__ int   g_rank[M_S];
__device__ float g_sval[M_S];      // value at sorted position
__device__ int   g_prtR[4*M_S];    // partial rank counts
__device__ int   g_prtE[4*M_S];    // partial edge-rank counts
__device__ uint4 g_erec[N_E];      // sorted edge records

// Order-preserving map float -> uint32
__device__ __forceinline__ unsigned int fsort(float x) {
    unsigned int u = __float_as_uint(x);
    return (u & 0x80000000u) ? ~u : (u | 0x80000000u);
}

// analytic edge endpoints (matches _build_complex exactly)
__device__ __forceinline__ void edge_uv(int e, int& u, int& v) {
    if (e < A_NH) {                 // horizontal
        int r = e / (WW-1), c = e % (WW-1);
        u = r * WW + c; v = u + 1;
    } else if (e < A_NH + A_NV) {   // vertical
        int k = e - A_NH;
        int r = k / WW, c = k % WW;
        u = r * WW + c; v = u + WW;
    } else {                        // anti-diagonal (v01, v10)
        int k = e - A_NH - A_NV;
        int r = k / (WW-1), c = k % (WW-1);
        u = r * WW + c + 1; v = (r + 1) * WW + c;
    }
}

// analytic edge -> triangle cofaces (c0 <= c1; c0==c1 iff boundary edge)
__device__ __forceinline__ void edge_cof(int e, int& c0, int& c1) {
    if (e < A_NH) {
        int r = e / (WW-1), c = e % (WW-1);
        int tA = r * (WW-1) + c;                 // valid if r < HH-1
        int tB = TRI_A + (r-1) * (WW-1) + c;     // valid if r >= 1
        if (r == 0)            { c0 = c1 = tA; }
        else if (r == HH-1)    { c0 = c1 = tB; }
        else                   { c0 = tA; c1 = tB; }
    } else if (e < A_NH + A_NV) {
        int k = e - A_NH;
        int r = k / WW, c = k % WW;
        int tA = r * (WW-1) + c;                 // valid if c < WW-1
        int tB = TRI_A + r * (WW-1) + (c-1);     // valid if c >= 1
        if (c == 0)            { c0 = c1 = tA; }
        else if (c == WW-1)    { c0 = c1 = tB; }
        else                   { c0 = tA; c1 = tB; }
    } else {
        int k = e - A_NH - A_NV;
        c0 = k;                                   // triA(r,c) == k
        c1 = TRI_A + k;                           // triB(r,c)
    }
}

// ---------------------------------------------------------------------------
// K1: per-simplex filtration values + sort keys (all analytic); zero output
// ---------------------------------------------------------------------------
__global__ void k_vals(const float* __restrict__ img,
                       float* __restrict__ out, int out_n)
{
    int s   = blockIdx.x * blockDim.x + threadIdx.x;
    int gsz = gridDim.x * blockDim.x;
    for (int o = s; o < out_n; o += gsz) out[o] = 0.0f;   // clear poisoned output
    if (s >= M_S) return;

    float v;
    if (s < N_V) {
        v = img[s];
    } else if (s < N_V + N_E) {
        int u0, v0;
        edge_uv(s - N_V, u0, v0);
        v = fmaxf(img[u0], img[v0]);
    } else {
        int t = s - N_V - N_E;
        if (t < TRI_A) {
            int rr = t / (WW-1), cc = t % (WW-1);
            int b  = rr * WW + cc;
            v = fmaxf(img[b], fmaxf(img[b+1], img[b+WW]));       // v00,v01,v10
        } else {
            int tt = t - TRI_A;
            int rr = tt / (WW-1), cc = tt % (WW-1);
            int b  = rr * WW + cc;
            v = fmaxf(img[b+1], fmaxf(img[b+WW], img[b+WW+1]));  // v01,v10,v11
        }
    }
    g_vals[s] = v;
    // key = (sortable value, original index); dim is monotone in index, so
    // this reproduces lexsort((dims, vals)) exactly.
    g_keys[s] = ((u64)fsort(v) << 32) | (unsigned int)s;
}

// ---------------------------------------------------------------------------
// K2: partial rank counting. Grid (53, 4): block (bs, q) counts how many keys
// in quarter-chunk q are below each simplex's key. 4x more parallelism than a
// monolithic count.
// ---------------------------------------------------------------------------
static constexpr int QCH = (M_S + 3) / 4;   // 3361

__global__ void k_cnt()
{
    __shared__ u64 sk[QCH];
    int q   = blockIdx.y;
    int s   = blockIdx.x * blockDim.x + threadIdx.x;
    int qb  = q * QCH;
    int qn  = min(QCH, M_S - qb);

    for (int j = threadIdx.x; j < qn; j += blockDim.x) sk[j] = g_keys[qb + j];
    __syncthreads();
    if (s >= M_S) return;

    u64 my = g_keys[s];
    int jLo = max(0, min(qn, N_V - qb));
    int jHi = max(jLo, min(qn, N_V + N_E - qb));
    int rank = 0, erank = 0;
    int j = 0;
    #pragma unroll 4
    for (; j < jLo; j++) rank += (sk[j] < my);
    #pragma unroll 4
    for (; j < jHi; j++) { bool lt = sk[j] < my; rank += lt; erank += lt; }
    #pragma unroll 4
    for (; j < qn; j++) rank += (sk[j] < my);

    g_prtR[q * M_S + s] = rank;
    g_prtE[q * M_S + s] = erank;
}

// ---------------------------------------------------------------------------
// K3: finalize ranks; build rank->value table, sorted edge records (with
// analytic endpoints/cofaces), and essential-H0 output row.
// ---------------------------------------------------------------------------
__global__ void k_fin(float* __restrict__ out)
{
    int s = blockIdx.x * blockDim.x + threadIdx.x;
    if (s >= M_S) return;

    int rank = g_prtR[s] + g_prtR[M_S + s] + g_prtR[2*M_S + s] + g_prtR[3*M_S + s];
    g_rank[s] = rank;
    float myval = g_vals[s];
    g_sval[rank] = myval;
    if (rank == 0)       out[0] = myval;   // essential H0 birth (global min)
    if (rank == M_S - 1) out[1] = myval;   // its death = fmax

    if (s >= N_V && s < N_V + N_E) {
        int erank = g_prtE[s] + g_prtE[M_S + s] + g_prtE[2*M_S + s] + g_prtE[3*M_S + s];
        int e = s - N_V;
        int u, v, c0, c1;
        edge_uv(e, u, v);
        edge_cof(e, c0, c1);
        uint4 r;
        r.x = (unsigned)u | ((unsigned)v << 16);
        r.y = __float_as_uint(myval);
        r.z = (unsigned)rank;
        r.w = (unsigned)c0 | ((unsigned)c1 << 16);
        g_erec[erank] = r;
    }
}

// ---------------------------------------------------------------------------
// K4: single block, 512 threads. No MST pre-filter:
//  A) stage edge endpoints (ex) and dual endpoints (ew) in sorted order
//  C) staged parallel CC -> per-segment UF snapshots at quarter cuts
//     (node word u32 = [root:16 | comp birth rank:16], fully compressed)
//  D) 8 concurrent serial UF threads over FULL edge-list quarters (branchless
//     identity-union on already-connected edges; emit dying rank or 0xFFFF)
//  E) parallel epilogue resolves values and writes diagram rows
// ---------------------------------------------------------------------------
// smem layout (bytes)
static constexpr int OFF_EX   = 0;                         // u32[N_E+1] 26888
static constexpr int OFF_EW   = 26888;                     // u32[N_E+1] 26888
static constexpr int OFF_LAB  = 53776;                     // u32[N1]    17676
static constexpr int OFF_RKM  = 71452;                     // u32[N1]    17676
static constexpr int OFF_SEG0 = 89128;                     // u32[4*N_V] 36864
static constexpr int OFF_SEG1 = 125992;                    // u32[4*N1]  70704
static constexpr int OFF_DR0  = 196696;                    // u16[N_E]   13442
static constexpr int OFF_DR1  = 210138;                    // u16[N_E]   13442
static constexpr int SMEM_BYTES = 223580;

__device__ static const int S0[5]  = {0, 1681, 3361, 5041, N_E};
__device__ static const int S1b[5] = {N_E, 5041, 3361, 1681, 0};

__device__ __forceinline__ int chase32(unsigned* L, int x) {
    int p = (int)L[x];
    while (p != x) { x = p; p = (int)L[x]; }
    return x;
}

// serial find with path halving on u32 packed words [parent:16 | rank:16]
__device__ __forceinline__ unsigned sfind(unsigned* __restrict__ sg, int x,
                                          unsigned w, int& root)
{
    for (;;) {
        int p = (int)(w >> 16);
        if (p == x) { root = x; return w; }
        unsigned wp = sg[p];
        int gp = (int)(wp >> 16);
        if (gp != p) sg[x] = (w & 0xffffu) | ((unsigned)gp << 16);
        x = p; w = wp;
    }
}

__global__ void __launch_bounds__(512, 1)
k_pair(float* __restrict__ out)
{
    extern __shared__ char smb[];
    unsigned* ex   = (unsigned*)(smb + OFF_EX);
    unsigned* ew   = (unsigned*)(smb + OFF_EW);
    unsigned* lab  = (unsigned*)(smb + OFF_LAB);
    unsigned* rkm  = (unsigned*)(smb + OFF_RKM);
    unsigned* seg0 = (unsigned*)(smb + OFF_SEG0);
    unsigned* seg1 = (unsigned*)(smb + OFF_SEG1);
    ushort*   dr0  = (ushort*)(smb + OFF_DR0);
    ushort*   dr1  = (ushort*)(smb + OFF_DR1);
    __shared__ int s_changed;

    int tid = threadIdx.x;

    // ---- A: stage edges in sorted order ----
    for (int e = tid; e < N_E; e += 512) {
        uint4 r = g_erec[e];
        ex[e] = r.x;
        unsigned c0 = r.w & 0xffffu, c1 = r.w >> 16;
        unsigned b  = (c1 == c0) ? (unsigned)N_F : c1;
        ew[e] = c0 | (b << 16);
    }
    if (tid == 0) { ex[N_E] = 0; ew[N_E] = 0; }

    // ---- C1: dim0 staged CC + quarter snapshots ----
    for (int v = tid; v < N_V; v += 512) {
        lab[v]  = (unsigned)v;
        seg0[v] = ((unsigned)v << 16) | (unsigned)g_rank[v];   // snapshot p=0
    }
    __syncthreads();
    for (int p = 1; p < 4; p++) {
        for (int round = 0; round < 24; round++) {
            if (tid == 0) s_changed = 0;
            __syncthreads();
            for (int j = S0[p-1] + tid; j < S0[p]; j += 512) {
                unsigned x = ex[j];
                int ra = chase32(lab, (int)(x & 0xffffu));
                int rb = chase32(lab, (int)(x >> 16));
                if (ra != rb) {
                    int mn = min(ra, rb), mx = max(ra, rb);
                    atomicMin(&lab[mx], (unsigned)mn);
                    s_changed = 1;
                }
            }
            __syncthreads();
            for (int v = tid; v < N_V; v += 512) {
                int r = (int)lab[v], pr = (int)lab[r];
                while (pr != r) { r = pr; pr = (int)lab[r]; }
                lab[v] = (unsigned)r;
            }
            __syncthreads();
            if (!s_changed) break;
        }
        for (int v = tid; v < N_V; v += 512) rkm[v] = 0xffffffffu;
        __syncthreads();
        for (int v = tid; v < N_V; v += 512)
            atomicMin(&rkm[lab[v]], seg0[v] & 0xffffu);   // rank(v) from p=0 snapshot
        __syncthreads();
        unsigned* sg = seg0 + p * N_V;
        for (int v = tid; v < N_V; v += 512)
            sg[v] = (lab[v] << 16) | (rkm[lab[v]] & 0xffffu);
        __syncthreads();
    }

    // ---- C2: dim1 staged CC + quarter snapshots (dual graph, MAX rank) ----
    for (int t = tid; t < N1; t += 512) {
        unsigned rk = (t < N_F) ? (unsigned)g_rank[N_V + N_E + t] : (unsigned)M_S;
        lab[t]  = (unsigned)t;
        seg1[t] = ((unsigned)t << 16) | rk;               // snapshot p=0
    }
    __syncthreads();
    for (int p = 1; p < 4; p++) {
        for (int round = 0; round < 24; round++) {
            if (tid == 0) s_changed = 0;
            __syncthreads();
            for (int j = S1b[p] + tid; j < S1b[p-1]; j += 512) {
                unsigned x = ew[j];
                int ra = chase32(lab, (int)(x & 0xffffu));
                int rb = chase32(lab, (int)(x >> 16));
                if (ra != rb) {
                    int mn = min(ra, rb), mx = max(ra, rb);
                    atomicMin(&lab[mx], (unsigned)mn);
                    s_changed = 1;
                }
            }
            __syncthreads();
            for (int t = tid; t < N1; t += 512) {
                int r = (int)lab[t], pr = (int)lab[r];
                while (pr != r) { r = pr; pr = (int)lab[r]; }
                lab[t] = (unsigned)r;
            }
            __syncthreads();
            if (!s_changed) break;
        }
        for (int t = tid; t < N1; t += 512) rkm[t] = 0u;
        __syncthreads();
        for (int t = tid; t < N1; t += 512)
            atomicMax(&rkm[lab[t]], seg1[t] & 0xffffu);   // rank from p=0 snapshot
        __syncthreads();
        unsigned* sg = seg1 + p * N1;
        for (int t = tid; t < N1; t += 512)
            sg[t] = (lab[t] << 16) | (rkm[lab[t]] & 0xffffu);
        __syncthreads();
    }

    // ---- D: 8 concurrent serial UF threads over full quarters ----
    int wid = tid >> 5, lane = tid & 31;
    if (lane == 0 && wid < 4) {
        // dim0 segment wid: increasing order; dying = LARGER birth rank
        int p = wid;
        unsigned* sg = seg0 + p * N_V;
        int lo = S0[p], hi = S0[p + 1];
        int lastIdx = -1; unsigned lastW = 0;
        unsigned x = ex[lo];
        int u = (int)(x & 0xffffu), v = (int)(x >> 16);
        unsigned wu = sg[u], wv = sg[v];
        for (int j = lo; j < hi; j++) {
            unsigned x2 = ex[j + 1];                       // sentinel at N_E
            int un = (int)(x2 & 0xffffu), vn = (int)(x2 >> 16);
            unsigned wun = sg[un], wvn = sg[vn];
            if (u == lastIdx) wu = lastW;
            if (v == lastIdx) wv = lastW;
            int pu = (int)(wu >> 16), pv = (int)(wv >> 16);
            unsigned wpu = sg[pu], wpv = sg[pv];
            bool fu = (pu == u), fv = (pv == v);
            int ru, rv; unsigned wru, wrv;
            if (__builtin_expect((int)(((!fu) & ((int)(wpu >> 16) != pu)) |
                                       ((!fv) & ((int)(wpv >> 16) != pv))), 0)) {
                wru = sfind(sg, u, wu, ru);
                wrv = sfind(sg, v, wv, rv);
            } else {
                ru = fu ? u : pu;  wru = fu ? wu : wpu;
                rv = fv ? v : pv;  wrv = fv ? wv : wpv;
            }
            sg[u] = ((unsigned)ru << 16) | (wru & 0xffffu);
            sg[v] = ((unsigned)rv << 16) | (wrv & 0xffffu);
            // branchless union: if roots equal this degenerates to identity
            bool eq = (ru == rv);
            int bu = (int)(wru & 0xffffu), bv = (int)(wrv & 0xffffu);
            bool uy = (bu > bv);                // u-side younger -> dies
            int y = uy ? ru : rv;
            unsigned wsur = uy ? wrv : wru;
            dr0[j] = eq ? (ushort)0xffffu : (ushort)(uy ? bu : bv);
            sg[y] = wsur;
            lastIdx = y; lastW = wsur;
            u = un; v = vn; wu = wun; wv = wvn;
        }
    } else if (lane == 0 && wid < 8) {
        // dim1 segment wid-4: decreasing order (dual); dying = SMALLER max rank
        int p = wid - 4;
        unsigned* sg = seg1 + p * N1;
        int start = S1b[p] - 1, end = S1b[p + 1];
        int lastIdx = -1; unsigned lastW = 0;
        unsigned x = ew[start];
        int a = (int)(x & 0xffffu), b = (int)(x >> 16);
        unsigned wa = sg[a], wb = sg[b];
        for (int j = start; j >= end; j--) {
            int jn = max(j - 1, 0);
            unsigned x2 = ew[jn];
            int an = (int)(x2 & 0xffffu), bn = (int)(x2 >> 16);
            unsigned wan = sg[an], wbn = sg[bn];
            if (a == lastIdx) wa = lastW;
            if (b == lastIdx) wb = lastW;
            int pa = (int)(wa >> 16), pb = (int)(wb >> 16);
            unsigned wpa = sg[pa], wpb = sg[pb];
            bool fa = (pa == a), fb = (pb == b);
            int ra, rb; unsigned wra, wrb;
            if (__builtin_expect((int)(((!fa) & ((int)(wpa >> 16) != pa)) |
                                       ((!fb) & ((int)(wpb >> 16) != pb))), 0)) {
                wra = sfind(sg, a, wa, ra);
                wrb = sfind(sg, b, wb, rb);
            } else {
                ra = fa ? a : pa;  wra = fa ? wa : wpa;
                rb = fb ? b : pb;  wrb = fb ? wb : wpb;
            }
            sg[a] = ((unsigned)ra << 16) | (wra & 0xffffu);
            sg[b] = ((unsigned)rb << 16) | (wrb & 0xffffu);
            bool eq = (ra == rb);
            int ba = (int)(wra & 0xffffu), bb = (int)(wrb & 0xffffu);
            bool ad = (ba < bb);                // a-side dies
            int y = ad ? ra : rb;
            unsigned wsur = ad ? wrb : wra;
            dr1[j] = eq ? (ushort)0xffffu : (ushort)(ad ? ba : bb);
            sg[y] = wsur;
            lastIdx = y; lastW = wsur;
            a = an; b = bn; wa = wan; wb = wbn;
        }
    }
    __syncthreads();

    // ---- E: parallel epilogue (resolve values, write diagram rows) ----
    float2* o0 = (float2*)out;
    float2* o1 = o0 + M_S;
    for (int j = tid; j < N_E; j += 512) {
        uint4 r = g_erec[j];
        int d0 = dr0[j];
        if (d0 != 0xffff)
            o0[d0] = make_float2(g_sval[d0], __uint_as_float(r.y));
        int d1 = dr1[j];
        if (d1 != 0xffff)
            o1[(int)r.z] = make_float2(__uint_as_float(r.y), g_sval[d1]);
    }
}

// ---------------------------------------------------------------------------
extern "C" void kernel_launch(void* const* d_in, const int* in_sizes, int n_in,
                              void* d_out, int out_size)
{
    const float* img = (const float*)d_in[0];
    float*       out = (float*)d_out;

    cudaFuncSetAttribute(k_pair, cudaFuncAttributeMaxDynamicSharedMemorySize, SMEM_BYTES);

    k_vals<<<(M_S + 255) / 256, 256>>>(img, out, out_size);
    k_cnt <<<dim3((M_S + 255) / 256, 4), 256>>>();
    k_fin <<<(M_S + 255) / 256, 256>>>(out);
    k_pair<<<1, 512, SMEM_BYTES>>>(out);
}

// round 9
// speedup vs baseline: 29.9966x; 1.4757x over previous
#include <cuda_runtime.h>
#include <stdint.h>

// Problem constants (fixed-shape problem: 48x48 grid, regular triangulation)
static constexpr int HH   = 48;
static constexpr int WW   = 48;
static constexpr int N_V  = HH * WW;                                          // 2304
static constexpr int N_E  = HH*(WW-1) + (HH-1)*WW + (HH-1)*(WW-1);            // 6721
static constexpr int N_F  = 2*(HH-1)*(WW-1);                                  // 4418
static constexpr int M_S  = N_V + N_E + N_F;                                  // 13443
static constexpr int N1   = N_F + 1;                                          // 4419 dual nodes

// analytic complex constants
static constexpr int A_NH = HH*(WW-1);        // 2256 horizontal edges
static constexpr int A_NV = (HH-1)*WW;        // 2256 vertical edges
static constexpr int TRI_A = (HH-1)*(WW-1);   // 2209 (# of A-triangles)

typedef unsigned long long u64;

// Global scratch (no allocations allowed)
__device__ float    g_vals[M_S];
__device__ u64      g_keys[M_S];
__device__ int      g_rank[M_S];
__device__ float    g_sval[M_S];       // value at sorted position
__device__ int      g_prtR[8*M_S];     // partial rank counts
__device__ int      g_prtE[8*M_S];     // partial edge-rank counts
__device__ uint4    g_erec[N_E];       // sorted edge records
__device__ unsigned g_ex[N_E + 1];     // sorted edge endpoints (u | v<<16), +sentinel
__device__ unsigned g_ew[N_E + 1];     // sorted dual endpoints (c0 | b<<16), +sentinel
__device__ ushort   g_dr0[N_E];        // dim0 dying rank per sorted edge (0xffff = none)
__device__ ushort   g_dr1[N_E];        // dim1 dying rank per sorted edge

// Order-preserving map float -> uint32
__device__ __forceinline__ unsigned int fsort(float x) {
    unsigned int u = __float_as_uint(x);
    return (u & 0x80000000u) ? ~u : (u | 0x80000000u);
}

// analytic edge endpoints (matches _build_complex exactly)
__device__ __forceinline__ void edge_uv(int e, int& u, int& v) {
    if (e < A_NH) {                 // horizontal
        int r = e / (WW-1), c = e % (WW-1);
        u = r * WW + c; v = u + 1;
    } else if (e < A_NH + A_NV) {   // vertical
        int k = e - A_NH;
        int r = k / WW, c = k % WW;
        u = r * WW + c; v = u + WW;
    } else {                        // anti-diagonal (v01, v10)
        int k = e - A_NH - A_NV;
        int r = k / (WW-1), c = k % (WW-1);
        u = r * WW + c + 1; v = (r + 1) * WW + c;
    }
}

// analytic edge -> triangle cofaces (c0==c1 iff boundary edge)
__device__ __forceinline__ void edge_cof(int e, int& c0, int& c1) {
    if (e < A_NH) {
        int r = e / (WW-1), c = e % (WW-1);
        int tA = r * (WW-1) + c;
        int tB = TRI_A + (r-1) * (WW-1) + c;
        if (r == 0)            { c0 = c1 = tA; }
        else if (r == HH-1)    { c0 = c1 = tB; }
        else                   { c0 = tA; c1 = tB; }
    } else if (e < A_NH + A_NV) {
        int k = e - A_NH;
        int r = k / WW, c = k % WW;
        int tA = r * (WW-1) + c;
        int tB = TRI_A + r * (WW-1) + (c-1);
        if (c == 0)            { c0 = c1 = tA; }
        else if (c == WW-1)    { c0 = c1 = tB; }
        else                   { c0 = tA; c1 = tB; }
    } else {
        int k = e - A_NH - A_NV;
        c0 = k;
        c1 = TRI_A + k;
    }
}

// ---------------------------------------------------------------------------
// K1: per-simplex filtration values + sort keys (all analytic); zero output
// ---------------------------------------------------------------------------
__global__ void k_vals(const float* __restrict__ img,
                       float* __restrict__ out, int out_n)
{
    int s   = blockIdx.x * blockDim.x + threadIdx.x;
    int gsz = gridDim.x * blockDim.x;
    for (int o = s; o < out_n; o += gsz) out[o] = 0.0f;   // clear poisoned output
    if (s == 0) { g_ex[N_E] = 0; g_ew[N_E] = 0; }         // prefetch sentinels
    if (s >= M_S) return;

    float v;
    if (s < N_V) {
        v = img[s];
    } else if (s < N_V + N_E) {
        int u0, v0;
        edge_uv(s - N_V, u0, v0);
        v = fmaxf(img[u0], img[v0]);
    } else {
        int t = s - N_V - N_E;
        if (t < TRI_A) {
            int rr = t / (WW-1), cc = t % (WW-1);
            int b  = rr * WW + cc;
            v = fmaxf(img[b], fmaxf(img[b+1], img[b+WW]));       // v00,v01,v10
        } else {
            int tt = t - TRI_A;
            int rr = tt / (WW-1), cc = tt % (WW-1);
            int b  = rr * WW + cc;
            v = fmaxf(img[b+1], fmaxf(img[b+WW], img[b+WW+1]));  // v01,v10,v11
        }
    }
    g_vals[s] = v;
    // key = (sortable value, original index); dim is monotone in index, so
    // this reproduces lexsort((dims, vals)) exactly.
    g_keys[s] = ((u64)fsort(v) << 32) | (unsigned int)s;
}

// ---------------------------------------------------------------------------
// K2: partial rank counting, 8 key chunks. Block (bs, q) counts keys in chunk
// q below each simplex key.
// ---------------------------------------------------------------------------
static constexpr int QCH = (M_S + 7) / 8;   // 1681

__global__ void k_cnt()
{
    __shared__ u64 sk[QCH];
    int q   = blockIdx.y;
    int s   = blockIdx.x * blockDim.x + threadIdx.x;
    int qb  = q * QCH;
    int qn  = min(QCH, M_S - qb);

    for (int j = threadIdx.x; j < qn; j += blockDim.x) sk[j] = g_keys[qb + j];
    __syncthreads();
    if (s >= M_S) return;

    u64 my = g_keys[s];
    int jLo = max(0, min(qn, N_V - qb));
    int jHi = max(jLo, min(qn, N_V + N_E - qb));
    int rank = 0, erank = 0;
    int j = 0;
    #pragma unroll 4
    for (; j < jLo; j++) rank += (sk[j] < my);
    #pragma unroll 4
    for (; j < jHi; j++) { bool lt = sk[j] < my; rank += lt; erank += lt; }
    #pragma unroll 4
    for (; j < qn; j++) rank += (sk[j] < my);

    g_prtR[q * M_S + s] = rank;
    g_prtE[q * M_S + s] = erank;
}

// ---------------------------------------------------------------------------
// K3: finalize ranks; build rank->value table, sorted edge tables (analytic
// endpoints/cofaces), and the essential-H0 output row.
// ---------------------------------------------------------------------------
__global__ void k_fin(float* __restrict__ out)
{
    int s = blockIdx.x * blockDim.x + threadIdx.x;
    if (s >= M_S) return;

    int rank = 0;
    #pragma unroll
    for (int q = 0; q < 8; q++) rank += g_prtR[q * M_S + s];
    g_rank[s] = rank;
    float myval = g_vals[s];
    g_sval[rank] = myval;
    if (rank == 0)       out[0] = myval;   // essential H0 birth (global min)
    if (rank == M_S - 1) out[1] = myval;   // its death = fmax

    if (s >= N_V && s < N_V + N_E) {
        int erank = 0;
        #pragma unroll
        for (int q = 0; q < 8; q++) erank += g_prtE[q * M_S + s];
        int e = s - N_V;
        int u, v, c0, c1;
        edge_uv(e, u, v);
        edge_cof(e, c0, c1);
        uint4 r;
        r.x = (unsigned)u | ((unsigned)v << 16);
        r.y = __float_as_uint(myval);
        r.z = (unsigned)rank;
        r.w = (unsigned)c0 | ((unsigned)c1 << 16);
        g_erec[erank] = r;
        g_ex[erank] = r.x;
        unsigned b = (c1 == c0) ? (unsigned)N_F : (unsigned)c1;
        g_ew[erank] = (unsigned)c0 | (b << 16);
    }
}

// ---------------------------------------------------------------------------
// K4: grid=2, 512 threads/block. Block 0 = dim0 pipeline, block 1 = dim1
// pipeline (independent SMs, no contention).
// Per block: staged parallel CC -> 8 per-segment UF snapshots at cuts
// (node word u32 = [root:16 | comp birth rank:16], fully compressed), then
// 8 concurrent serial UF threads over eighths of the sorted edge list
// (branchless identity-union on already-connected edges; emit dying rank or
// 0xffff to global), then parallel epilogue writes diagram rows.
// ---------------------------------------------------------------------------
static constexpr int SMEM_BYTES = (8*N1 + 2*N1) * 4 + 64;   // 176824 (dim1 is max)

__device__ static const int CUT[9] = {0, 841, 1681, 2521, 3361, 4201, 5041, 5881, N_E};

__device__ __forceinline__ int chase32(unsigned* L, int x) {
    int p = (int)L[x];
    while (p != x) { x = p; p = (int)L[x]; }
    return x;
}

// serial find with path halving on u32 packed words [parent:16 | rank:16]
__device__ __forceinline__ unsigned sfind(unsigned* __restrict__ sg, int x,
                                          unsigned w, int& root)
{
    for (;;) {
        int p = (int)(w >> 16);
        if (p == x) { root = x; return w; }
        unsigned wp = sg[p];
        int gp = (int)(wp >> 16);
        if (gp != p) sg[x] = (w & 0xffffu) | ((unsigned)gp << 16);
        x = p; w = wp;
    }
}

__global__ void __launch_bounds__(512, 1)
k_pair(float* __restrict__ out)
{
    extern __shared__ unsigned smu[];
    __shared__ int s_changed;
    int tid  = threadIdx.x;
    int wid  = tid >> 5, lane = tid & 31;

    if (blockIdx.x == 0) {
        // ======================= DIM 0 (primal, forward) =======================
        unsigned* seg = smu;                 // [8*N_V]
        unsigned* lab = seg + 8*N_V;         // [N_V]
        unsigned* rkm = lab + N_V;           // [N_V]

        for (int v = tid; v < N_V; v += 512) {
            lab[v] = (unsigned)v;
            seg[v] = ((unsigned)v << 16) | (unsigned)g_rank[v];   // p=0 snapshot
        }
        __syncthreads();

        for (int p = 1; p < 8; p++) {
            for (int round = 0; round < 24; round++) {
                if (tid == 0) s_changed = 0;
                __syncthreads();
                for (int j = CUT[p-1] + tid; j < CUT[p]; j += 512) {
                    unsigned x = g_ex[j];
                    int ra = chase32(lab, (int)(x & 0xffffu));
                    int rb = chase32(lab, (int)(x >> 16));
                    if (ra != rb) {
                        int mn = min(ra, rb), mx = max(ra, rb);
                        atomicMin(&lab[mx], (unsigned)mn);
                        s_changed = 1;
                    }
                }
                __syncthreads();
                for (int v = tid; v < N_V; v += 512) {
                    int r = (int)lab[v], pr = (int)lab[r];
                    while (pr != r) { r = pr; pr = (int)lab[r]; }
                    lab[v] = (unsigned)r;
                }
                __syncthreads();
                if (!s_changed) break;
            }
            for (int v = tid; v < N_V; v += 512) rkm[v] = 0xffffffffu;
            __syncthreads();
            for (int v = tid; v < N_V; v += 512)
                atomicMin(&rkm[lab[v]], seg[v] & 0xffffu);   // own rank from p=0
            __syncthreads();
            unsigned* sg = seg + p * N_V;
            for (int v = tid; v < N_V; v += 512)
                sg[v] = (lab[v] << 16) | (rkm[lab[v]] & 0xffffu);
            __syncthreads();
        }

        // ---- 8 concurrent serial UF threads; dying = LARGER birth rank ----
        if (lane == 0 && wid < 8) {
            unsigned* sg = seg + wid * N_V;
            int lo = CUT[wid], hi = CUT[wid + 1];
            int lastIdx = -1; unsigned lastW = 0;
            unsigned x = g_ex[lo];
            int u = (int)(x & 0xffffu), v = (int)(x >> 16);
            unsigned wu = sg[u], wv = sg[v];
            for (int j = lo; j < hi; j++) {
                unsigned x2 = g_ex[j + 1];                  // sentinel at N_E
                int un = (int)(x2 & 0xffffu), vn = (int)(x2 >> 16);
                unsigned wun = sg[un], wvn = sg[vn];
                if (u == lastIdx) wu = lastW;
                if (v == lastIdx) wv = lastW;
                int pu = (int)(wu >> 16), pv = (int)(wv >> 16);
                unsigned wpu = sg[pu], wpv = sg[pv];
                bool fu = (pu == u), fv = (pv == v);
                int ru, rv; unsigned wru, wrv;
                if (__builtin_expect((int)(((!fu) & ((int)(wpu >> 16) != pu)) |
                                           ((!fv) & ((int)(wpv >> 16) != pv))), 0)) {
                    wru = sfind(sg, u, wu, ru);
                    wrv = sfind(sg, v, wv, rv);
                } else {
                    ru = fu ? u : pu;  wru = fu ? wu : wpu;
                    rv = fv ? v : pv;  wrv = fv ? wv : wpv;
                }
                sg[u] = ((unsigned)ru << 16) | (wru & 0xffffu);
                sg[v] = ((unsigned)rv << 16) | (wrv & 0xffffu);
                bool eq = (ru == rv);
                int bu = (int)(wru & 0xffffu), bv = (int)(wrv & 0xffffu);
                bool uy = (bu > bv);                // larger birth rank dies
                int y = uy ? ru : rv;
                unsigned wsur = uy ? wrv : wru;
                g_dr0[j] = eq ? (ushort)0xffffu : (ushort)(uy ? bu : bv);
                sg[y] = wsur;
                lastIdx = y; lastW = wsur;
                u = un; v = vn; wu = wun; wv = wvn;
            }
        }
        __syncthreads();

        // ---- epilogue: dim0 diagram rows ----
        float2* o0 = (float2*)out;
        for (int j = tid; j < N_E; j += 512) {
            int d0 = g_dr0[j];
            if (d0 != 0xffff)
                o0[d0] = make_float2(g_sval[d0], __uint_as_float(g_erec[j].y));
        }
    } else {
        // ================== DIM 1 (dual, reversed order) ==================
        unsigned* seg = smu;                 // [8*N1]
        unsigned* lab = seg + 8*N1;          // [N1]
        unsigned* rkm = lab + N1;            // [N1]

        for (int t = tid; t < N1; t += 512) {
            unsigned rk = (t < N_F) ? (unsigned)g_rank[N_V + N_E + t] : (unsigned)M_S;
            lab[t] = (unsigned)t;
            seg[t] = ((unsigned)t << 16) | rk;               // p=0 snapshot
        }
        __syncthreads();

        for (int p = 1; p < 8; p++) {
            // stage p adds edges [CUT[8-p], CUT[9-p]) (the next suffix slab)
            for (int round = 0; round < 24; round++) {
                if (tid == 0) s_changed = 0;
                __syncthreads();
                for (int j = CUT[8-p] + tid; j < CUT[9-p]; j += 512) {
                    unsigned x = g_ew[j];
                    int ra = chase32(lab, (int)(x & 0xffffu));
                    int rb = chase32(lab, (int)(x >> 16));
                    if (ra != rb) {
                        int mn = min(ra, rb), mx = max(ra, rb);
                        atomicMin(&lab[mx], (unsigned)mn);
                        s_changed = 1;
                    }
                }
                __syncthreads();
                for (int t = tid; t < N1; t += 512) {
                    int r = (int)lab[t], pr = (int)lab[r];
                    while (pr != r) { r = pr; pr = (int)lab[r]; }
                    lab[t] = (unsigned)r;
                }
                __syncthreads();
                if (!s_changed) break;
            }
            for (int t = tid; t < N1; t += 512) rkm[t] = 0u;
            __syncthreads();
            for (int t = tid; t < N1; t += 512)
                atomicMax(&rkm[lab[t]], seg[t] & 0xffffu);   // own rank from p=0
            __syncthreads();
            unsigned* sg = seg + p * N1;
            for (int t = tid; t < N1; t += 512)
                sg[t] = (lab[t] << 16) | (rkm[lab[t]] & 0xffffu);
            __syncthreads();
        }

        // ---- 8 concurrent serial UF threads; dying = SMALLER max rank ----
        if (lane == 0 && wid < 8) {
            unsigned* sg = seg + wid * N1;
            int start = CUT[8 - wid] - 1, end = CUT[7 - wid];
            int lastIdx = -1; unsigned lastW = 0;
            unsigned x = g_ew[start];
            int a = (int)(x & 0xffffu), b = (int)(x >> 16);
            unsigned wa = sg[a], wb = sg[b];
            for (int j = start; j >= end; j--) {
                int jn = max(j - 1, 0);
                unsigned x2 = g_ew[jn];
                int an = (int)(x2 & 0xffffu), bn = (int)(x2 >> 16);
                unsigned wan = sg[an], wbn = sg[bn];
                if (a == lastIdx) wa = lastW;
                if (b == lastIdx) wb = lastW;
                int pa = (int)(wa >> 16), pb = (int)(wb >> 16);
                unsigned wpa = sg[pa], wpb = sg[pb];
                bool fa = (pa == a), fb = (pb == b);
                int ra, rb; unsigned wra, wrb;
                if (__builtin_expect((int)(((!fa) & ((int)(wpa >> 16) != pa)) |
                                           ((!fb) & ((int)(wpb >> 16) != pb))), 0)) {
                    wra = sfind(sg, a, wa, ra);
                    wrb = sfind(sg, b, wb, rb);
                } else {
                    ra = fa ? a : pa;  wra = fa ? wa : wpa;
                    rb = fb ? b : pb;  wrb = fb ? wb : wpb;
                }
                sg[a] = ((unsigned)ra << 16) | (wra & 0xffffu);
                sg[b] = ((unsigned)rb << 16) | (wrb & 0xffffu);
                bool eq = (ra == rb);
                int ba = (int)(wra & 0xffffu), bb = (int)(wrb & 0xffffu);
                bool ad = (ba < bb);                // smaller max rank dies
                int y = ad ? ra : rb;
                unsigned wsur = ad ? wrb : wra;
                g_dr1[j] = eq ? (ushort)0xffffu : (ushort)(ad ? ba : bb);
                sg[y] = wsur;
                lastIdx = y; lastW = wsur;
                a = an; b = bn; wa = wan; wb = wbn;
            }
        }
        __syncthreads();

        // ---- epilogue: dim1 diagram rows ----
        float2* o1 = (float2*)out + M_S;
        for (int j = tid; j < N_E; j += 512) {
            int d1 = g_dr1[j];
            if (d1 != 0xffff) {
                uint4 r = g_erec[j];
                o1[(int)r.z] = make_float2(__uint_as_float(r.y), g_sval[d1]);
            }
        }
    }
}

// ---------------------------------------------------------------------------
extern "C" void kernel_launch(void* const* d_in, const int* in_sizes, int n_in,
                              void* d_out, int out_size)
{
    const float* img = (const float*)d_in[0];
    float*       out = (float*)d_out;

    cudaFuncSetAttribute(k_pair, cudaFuncAttributeMaxDynamicSharedMemorySize, SMEM_BYTES);

    k_vals<<<(M_S + 255) / 256, 256>>>(img, out, out_size);
    k_cnt <<<dim3((M_S + 255) / 256, 8), 256>>>();
    k_fin <<<(M_S + 255) / 256, 256>>>(out);
    k_pair<<<2, 512, SMEM_BYTES>>>(out);
}

// round 10
// speedup vs baseline: 42.5003x; 1.4168x over previous
#include <cuda_runtime.h>
#include <stdint.h>

// Problem constants (fixed-shape problem: 48x48 grid, regular triangulation)
static constexpr int HH   = 48;
static constexpr int WW   = 48;
static constexpr int N_V  = HH * WW;                                          // 2304
static constexpr int N_E  = HH*(WW-1) + (HH-1)*WW + (HH-1)*(WW-1);            // 6721
static constexpr int N_F  = 2*(HH-1)*(WW-1);                                  // 4418
static constexpr int M_S  = N_V + N_E + N_F;                                  // 13443
static constexpr int N1   = N_F + 1;                                          // 4419 dual nodes

// analytic complex constants
static constexpr int A_NH = HH*(WW-1);        // 2256 horizontal edges
static constexpr int A_NV = (HH-1)*WW;        // 2256 vertical edges
static constexpr int TRI_A = (HH-1)*(WW-1);   // 2209

static constexpr int PREP_BLOCKS = 424;       // 53 * 8

typedef unsigned long long u64;

// Global scratch (no allocations allowed)
__device__ float    g_vals[M_S];
__device__ u64      g_keys[M_S];
__device__ int      g_rank[M_S];
__device__ float    g_sval[M_S];
__device__ int      g_prtR[8*M_S];
__device__ int      g_prtE[8*M_S];
__device__ uint4    g_erec[N_E];
__device__ unsigned g_ex[N_E + 1];     // sorted edge endpoints (u | v<<16) + sentinel
__device__ unsigned g_ew[N_E + 1];     // sorted dual endpoints (c0 | b<<16) + sentinel
__device__ ushort   g_dr0[N_E];        // dim0 dying rank per sorted edge (0xffff = none)
__device__ ushort   g_dr1[N_E];        // dim1 dying rank per sorted edge
__device__ int      g_c1 = 0, g_c2 = 0, g_c3 = 0;   // software barrier counters

// Order-preserving map float -> uint32
__device__ __forceinline__ unsigned int fsort(float x) {
    unsigned int u = __float_as_uint(x);
    return (u & 0x80000000u) ? ~u : (u | 0x80000000u);
}

// software grid barrier (all blocks must be co-resident; they are: see launch)
__device__ __forceinline__ void gbar(int* c, int target) {
    __syncthreads();
    if (threadIdx.x == 0) {
        __threadfence();
        atomicAdd(c, 1);
        while (__ldcg((const int*)c) < target) __nanosleep(64);
    }
    __syncthreads();
}

// analytic edge endpoints (matches _build_complex exactly)
__device__ __forceinline__ void edge_uv(int e, int& u, int& v) {
    if (e < A_NH) {
        int r = e / (WW-1), c = e % (WW-1);
        u = r * WW + c; v = u + 1;
    } else if (e < A_NH + A_NV) {
        int k = e - A_NH;
        int r = k / WW, c = k % WW;
        u = r * WW + c; v = u + WW;
    } else {
        int k = e - A_NH - A_NV;
        int r = k / (WW-1), c = k % (WW-1);
        u = r * WW + c + 1; v = (r + 1) * WW + c;
    }
}

// analytic edge -> triangle cofaces (c0==c1 iff boundary edge)
__device__ __forceinline__ void edge_cof(int e, int& c0, int& c1) {
    if (e < A_NH) {
        int r = e / (WW-1), c = e % (WW-1);
        int tA = r * (WW-1) + c;
        int tB = TRI_A + (r-1) * (WW-1) + c;
        if (r == 0)            { c0 = c1 = tA; }
        else if (r == HH-1)    { c0 = c1 = tB; }
        else                   { c0 = tA; c1 = tB; }
    } else if (e < A_NH + A_NV) {
        int k = e - A_NH;
        int r = k / WW, c = k % WW;
        int tA = r * (WW-1) + c;
        int tB = TRI_A + r * (WW-1) + (c-1);
        if (c == 0)            { c0 = c1 = tA; }
        else if (c == WW-1)    { c0 = c1 = tB; }
        else                   { c0 = tA; c1 = tB; }
    } else {
        int k = e - A_NH - A_NV;
        c0 = k;
        c1 = TRI_A + k;
    }
}

// ---------------------------------------------------------------------------
// K_PREP: fused vals+keys -> partial rank counting -> finalize, with two
// software grid barriers. Grid = 424 x 256, all co-resident.
// ---------------------------------------------------------------------------
static constexpr int QCH = (M_S + 7) / 8;   // 1681

__global__ void __launch_bounds__(256)
k_prep(const float* __restrict__ img, float* __restrict__ out, int out_n)
{
    __shared__ u64 sk[QCH];
    int bid = blockIdx.x, tid = threadIdx.x;
    int g   = bid * 256 + tid;

    // ---- phase 1: zero output; per-simplex values + sort keys ----
    for (int o = g; o < out_n; o += PREP_BLOCKS * 256) out[o] = 0.0f;
    if (g == 0) { g_ex[N_E] = 0; g_ew[N_E] = 0; g_c3 = 0; }
    if (g < M_S) {
        int s = g;
        float v;
        if (s < N_V) {
            v = img[s];
        } else if (s < N_V + N_E) {
            int u0, v0;
            edge_uv(s - N_V, u0, v0);
            v = fmaxf(img[u0], img[v0]);
        } else {
            int t = s - N_V - N_E;
            if (t < TRI_A) {
                int rr = t / (WW-1), cc = t % (WW-1);
                int b  = rr * WW + cc;
                v = fmaxf(img[b], fmaxf(img[b+1], img[b+WW]));
            } else {
                int tt = t - TRI_A;
                int rr = tt / (WW-1), cc = tt % (WW-1);
                int b  = rr * WW + cc;
                v = fmaxf(img[b+1], fmaxf(img[b+WW], img[b+WW+1]));
            }
        }
        g_vals[s] = v;
        g_keys[s] = ((u64)fsort(v) << 32) | (unsigned int)s;
    }
    gbar(&g_c1, PREP_BLOCKS);

    // ---- phase 2: partial rank counting (q = chunk, sb = simplex block) ----
    {
        int q  = bid / 53;
        int sb = bid % 53;
        int s  = sb * 256 + tid;
        int qb = q * QCH;
        int qn = min(QCH, M_S - qb);
        for (int j = tid; j < qn; j += 256) sk[j] = g_keys[qb + j];
        __syncthreads();
        if (s < M_S) {
            u64 my = g_keys[s];
            int jLo = max(0, min(qn, N_V - qb));
            int jHi = max(jLo, min(qn, N_V + N_E - qb));
            int rank = 0, erank = 0;
            int j = 0;
            #pragma unroll 4
            for (; j < jLo; j++) rank += (sk[j] < my);
            #pragma unroll 4
            for (; j < jHi; j++) { bool lt = sk[j] < my; rank += lt; erank += lt; }
            #pragma unroll 4
            for (; j < qn; j++) rank += (sk[j] < my);
            g_prtR[q * M_S + s] = rank;
            g_prtE[q * M_S + s] = erank;
        }
    }
    gbar(&g_c2, PREP_BLOCKS);

    // ---- phase 3: finalize ----
    if (g < M_S) {
        int s = g;
        int rank = 0;
        #pragma unroll
        for (int q = 0; q < 8; q++) rank += g_prtR[q * M_S + s];
        g_rank[s] = rank;
        float myval = g_vals[s];
        g_sval[rank] = myval;
        if (rank == 0)       out[0] = myval;   // essential H0 birth
        if (rank == M_S - 1) out[1] = myval;   // its death = fmax

        if (s >= N_V && s < N_V + N_E) {
            int erank = 0;
            #pragma unroll
            for (int q = 0; q < 8; q++) erank += g_prtE[q * M_S + s];
            int e = s - N_V;
            int u, v, c0, c1;
            edge_uv(e, u, v);
            edge_cof(e, c0, c1);
            uint4 r;
            r.x = (unsigned)u | ((unsigned)v << 16);
            r.y = __float_as_uint(myval);
            r.z = (unsigned)rank;
            r.w = (unsigned)c0 | ((unsigned)c1 << 16);
            g_erec[erank] = r;
            g_ex[erank] = r.x;
            unsigned b = (c1 == c0) ? (unsigned)N_F : (unsigned)c1;
            g_ew[erank] = (unsigned)c0 | (b << 16);
        }
    }
}

// ---------------------------------------------------------------------------
// K_PAIR: grid=4, 512 threads. 16 segments total (8 per dim, 2 blocks/dim).
//   b0: dim0 segs 0-7   b1: dim0 segs 8-15 (bulk-hooks prefix first)
//   b2: dim1 segs 0-7   b3: dim1 segs 8-15 (bulk-hooks suffix first)
// Each block: staged parallel CC -> 8 UF snapshots (u32 [root:16|comprank:16]),
// 8 concurrent serial UF threads over 16ths of the sorted edge list, then a
// 4-block software barrier and a fused parallel epilogue.
// ---------------------------------------------------------------------------
static constexpr int SMEM_BYTES = (8*N1 + 2*N1) * 4 + 64;   // dim1 max ~176.8KB

__device__ static const int CUT16[17] = {
    0, 420, 840, 1260, 1680, 2100, 2520, 2940, 3360,
    3780, 4200, 4620, 5040, 5460, 5880, 6300, N_E };

__device__ __forceinline__ int chase32(unsigned* L, int x) {
    int p = (int)L[x];
    while (p != x) { x = p; p = (int)L[x]; }
    return x;
}

// serial find with path halving on u32 packed words [parent:16 | rank:16]
__device__ __forceinline__ unsigned sfind(unsigned* __restrict__ sg, int x,
                                          unsigned w, int& root)
{
    for (;;) {
        int p = (int)(w >> 16);
        if (p == x) { root = x; return w; }
        unsigned wp = sg[p];
        int gp = (int)(wp >> 16);
        if (gp != p) sg[x] = (w & 0xffffu) | ((unsigned)gp << 16);
        x = p; w = wp;
    }
}

// parallel CC hooking of edge slab [lo,hi) into lab[] (min-label), with full
// compression each round; converges (strictly decreasing labels).
__device__ __forceinline__ void cc_hook(unsigned* lab, const unsigned* __restrict__ earr,
                                        int lo, int hi, int nnodes, int tid,
                                        int* s_changed)
{
    for (int round = 0; round < 64; round++) {
        if (tid == 0) *s_changed = 0;
        __syncthreads();
        for (int j = lo + tid; j < hi; j += 512) {
            unsigned x = earr[j];
            int ra = chase32(lab, (int)(x & 0xffffu));
            int rb = chase32(lab, (int)(x >> 16));
            if (ra != rb) {
                int mn = min(ra, rb), mx = max(ra, rb);
                atomicMin(&lab[mx], (unsigned)mn);
                *s_changed = 1;
            }
        }
        __syncthreads();
        for (int v = tid; v < nnodes; v += 512) {
            int r = (int)lab[v], pr = (int)lab[r];
            while (pr != r) { r = pr; pr = (int)lab[r]; }
            lab[v] = (unsigned)r;
        }
        __syncthreads();
        if (!*s_changed) break;
    }
}

__global__ void __launch_bounds__(512, 1)
k_pair(float* __restrict__ out)
{
    extern __shared__ unsigned smu[];
    __shared__ int s_changed;
    int tid  = threadIdx.x;
    int wid  = tid >> 5, lane = tid & 31;
    int b    = blockIdx.x;

    if (b == 0 && tid == 0) { g_c1 = 0; g_c2 = 0; }  // reset k_prep's counters

    if (b < 2) {
        // ============================ DIM 0 ============================
        unsigned* seg = smu;
        unsigned* lab = seg + 8*N_V;
        unsigned* rkm = lab + N_V;
        int base = b * 8;   // first segment index

        for (int v = tid; v < N_V; v += 512) lab[v] = (unsigned)v;
        __syncthreads();

        for (int p = 0; p < 8; p++) {
            if (p == 0) {
                if (b == 1)   // bulk-hook prefix [0, CUT16[8])
                    cc_hook(lab, g_ex, 0, CUT16[8], N_V, tid, &s_changed);
            } else {
                cc_hook(lab, g_ex, CUT16[base+p-1], CUT16[base+p], N_V, tid, &s_changed);
            }
            // snapshot p: (root<<16 | comp-min-rank)
            for (int v = tid; v < N_V; v += 512) rkm[v] = 0xffffffffu;
            __syncthreads();
            for (int v = tid; v < N_V; v += 512)
                atomicMin(&rkm[lab[v]], (unsigned)g_rank[v]);
            __syncthreads();
            unsigned* sg = seg + p * N_V;
            for (int v = tid; v < N_V; v += 512)
                sg[v] = (lab[v] << 16) | (rkm[lab[v]] & 0xffffu);
            __syncthreads();
        }

        // ---- 8 concurrent serial UF threads; dying = LARGER birth rank ----
        if (lane == 0 && wid < 8) {
            unsigned* sg = seg + wid * N_V;
            int lo = CUT16[base + wid], hi = CUT16[base + wid + 1];
            int lastIdx = -1; unsigned lastW = 0;
            unsigned x = g_ex[lo];
            int u = (int)(x & 0xffffu), v = (int)(x >> 16);
            unsigned wu = sg[u], wv = sg[v];
            for (int j = lo; j < hi; j++) {
                unsigned x2 = g_ex[j + 1];
                int un = (int)(x2 & 0xffffu), vn = (int)(x2 >> 16);
                unsigned wun = sg[un], wvn = sg[vn];
                if (u == lastIdx) wu = lastW;
                if (v == lastIdx) wv = lastW;
                int pu = (int)(wu >> 16), pv = (int)(wv >> 16);
                unsigned wpu = sg[pu], wpv = sg[pv];
                bool fu = (pu == u), fv = (pv == v);
                int ru, rv; unsigned wru, wrv;
                if (__builtin_expect((int)(((!fu) & ((int)(wpu >> 16) != pu)) |
                                           ((!fv) & ((int)(wpv >> 16) != pv))), 0)) {
                    wru = sfind(sg, u, wu, ru);
                    wrv = sfind(sg, v, wv, rv);
                } else {
                    ru = fu ? u : pu;  wru = fu ? wu : wpu;
                    rv = fv ? v : pv;  wrv = fv ? wv : wpv;
                }
                sg[u] = ((unsigned)ru << 16) | (wru & 0xffffu);
                sg[v] = ((unsigned)rv << 16) | (wrv & 0xffffu);
                bool eq = (ru == rv);
                int bu = (int)(wru & 0xffffu), bv = (int)(wrv & 0xffffu);
                bool uy = (bu > bv);
                int y = uy ? ru : rv;
                unsigned wsur = uy ? wrv : wru;
                g_dr0[j] = eq ? (ushort)0xffffu : (ushort)(uy ? bu : bv);
                sg[y] = wsur;
                lastIdx = y; lastW = wsur;
                u = un; v = vn; wu = wun; wv = wvn;
            }
        }
    } else {
        // ==================== DIM 1 (dual, reversed) ====================
        unsigned* seg = smu;
        unsigned* lab = seg + 8*N1;
        unsigned* rkm = lab + N1;
        int base = (b - 2) * 8;

        for (int t = tid; t < N1; t += 512) lab[t] = (unsigned)t;
        __syncthreads();

        for (int p = 0; p < 8; p++) {
            if (p == 0) {
                if (b == 3)   // bulk-hook suffix [N_E-CUT16[8], N_E)
                    cc_hook(lab, g_ew, N_E - CUT16[8], N_E, N1, tid, &s_changed);
            } else {
                cc_hook(lab, g_ew, N_E - CUT16[base+p], N_E - CUT16[base+p-1],
                        N1, tid, &s_changed);
            }
            // snapshot p: (root<<16 | comp-MAX-rank)
            for (int t = tid; t < N1; t += 512) rkm[t] = 0u;
            __syncthreads();
            for (int t = tid; t < N1; t += 512) {
                unsigned rk = (t < N_F) ? (unsigned)g_rank[N_V + N_E + t]
                                        : (unsigned)M_S;
                atomicMax(&rkm[lab[t]], rk);
            }
            __syncthreads();
            unsigned* sg = seg + p * N1;
            for (int t = tid; t < N1; t += 512)
                sg[t] = (lab[t] << 16) | (rkm[lab[t]] & 0xffffu);
            __syncthreads();
        }

        // ---- 8 concurrent serial UF threads; dying = SMALLER max rank ----
        if (lane == 0 && wid < 8) {
            unsigned* sg = seg + wid * N1;
            int q = base + wid;
            int start = N_E - CUT16[q] - 1, end = N_E - CUT16[q + 1];
            int lastIdx = -1; unsigned lastW = 0;
            unsigned x = g_ew[start];
            int a = (int)(x & 0xffffu), bb0 = (int)(x >> 16);
            unsigned wa = sg[a], wb = sg[bb0];
            int bn_ = bb0;
            for (int j = start; j >= end; j--) {
                int jn = max(j - 1, 0);
                unsigned x2 = g_ew[jn];
                int an = (int)(x2 & 0xffffu), bn = (int)(x2 >> 16);
                unsigned wan = sg[an], wbn = sg[bn];
                if (a == lastIdx)   wa = lastW;
                if (bn_ == lastIdx) wb = lastW;
                int pa = (int)(wa >> 16), pb = (int)(wb >> 16);
                unsigned wpa = sg[pa], wpb = sg[pb];
                bool fa = (pa == a), fb = (pb == bn_);
                int ra, rb; unsigned wra, wrb;
                if (__builtin_expect((int)(((!fa) & ((int)(wpa >> 16) != pa)) |
                                           ((!fb) & ((int)(wpb >> 16) != pb))), 0)) {
                    wra = sfind(sg, a, wa, ra);
                    wrb = sfind(sg, bn_, wb, rb);
                } else {
                    ra = fa ? a : pa;    wra = fa ? wa : wpa;
                    rb = fb ? bn_ : pb;  wrb = fb ? wb : wpb;
                }
                sg[a]   = ((unsigned)ra << 16) | (wra & 0xffffu);
                sg[bn_] = ((unsigned)rb << 16) | (wrb & 0xffffu);
                bool eq = (ra == rb);
                int ba = (int)(wra & 0xffffu), bbr = (int)(wrb & 0xffffu);
                bool ad = (ba < bbr);
                int y = ad ? ra : rb;
                unsigned wsur = ad ? wrb : wra;
                g_dr1[j] = eq ? (ushort)0xffffu : (ushort)(ad ? ba : bbr);
                sg[y] = wsur;
                lastIdx = y; lastW = wsur;
                a = an; bn_ = bn; wa = wan; wb = wbn;
            }
        }
    }

    // ---- 4-block barrier, then fused epilogue ----
    gbar(&g_c3, 4);
    float2* o0 = (float2*)out;
    float2* o1 = o0 + M_S;
    for (int j = b * 512 + tid; j < N_E; j += 4 * 512) {
        uint4 r = g_erec[j];
        int d0 = g_dr0[j];
        if (d0 != 0xffff)
            o0[d0] = make_float2(g_sval[d0], __uint_as_float(r.y));
        int d1 = g_dr1[j];
        if (d1 != 0xffff)
            o1[(int)r.z] = make_float2(__uint_as_float(r.y), g_sval[d1]);
    }
}

// ---------------------------------------------------------------------------
extern "C" void kernel_launch(void* const* d_in, const int* in_sizes, int n_in,
                              void* d_out, int out_size)
{
    const float* img = (const float*)d_in[0];
    float*       out = (float*)d_out;

    cudaFuncSetAttribute(k_pair, cudaFuncAttributeMaxDynamicSharedMemorySize, SMEM_BYTES);

    k_prep<<<PREP_BLOCKS, 256>>>(img, out, out_size);
    k_pair<<<4, 512, SMEM_BYTES>>>(out);
}

// round 11
// speedup vs baseline: 50.0618x; 1.1779x over previous
#include <cuda_runtime.h>
#include <stdint.h>

// Problem constants (fixed-shape problem: 48x48 grid, regular triangulation)
static constexpr int HH   = 48;
static constexpr int WW   = 48;
static constexpr int N_V  = HH * WW;                                          // 2304
static constexpr int N_E  = HH*(WW-1) + (HH-1)*WW + (HH-1)*(WW-1);            // 6721
static constexpr int N_F  = 2*(HH-1)*(WW-1);                                  // 4418
static constexpr int M_S  = N_V + N_E + N_F;                                  // 13443
static constexpr int N1   = N_F + 1;                                          // 4419 dual nodes

// analytic complex constants
static constexpr int A_NH = HH*(WW-1);        // 2256 horizontal edges
static constexpr int A_NV = (HH-1)*WW;        // 2256 vertical edges
static constexpr int TRI_A = (HH-1)*(WW-1);   // 2209

static constexpr int PREP_BLOCKS = 424;       // 53 * 8
static constexpr int PAIR_BLOCKS = 8;

typedef unsigned long long u64;

// Global scratch (no allocations allowed)
__device__ float    g_vals[M_S];
__device__ u64      g_keys[M_S];
__device__ int      g_rank[M_S];
__device__ float    g_sval[M_S];
__device__ int      g_prtR[8*M_S];
__device__ int      g_prtE[8*M_S];
__device__ uint4    g_erec[N_E];
__device__ unsigned g_ex[N_E + 1];     // sorted edge endpoints (u | v<<16) + sentinel
__device__ unsigned g_ew[N_E + 1];     // sorted dual endpoints (c0 | b<<16) + sentinel
__device__ ushort   g_dr0[N_E];        // dim0 dying rank per sorted edge (0xffff = none)
__device__ ushort   g_dr1[N_E];        // dim1 dying rank per sorted edge
__device__ int      g_c1 = 0, g_c2 = 0, g_c3 = 0;   // software barrier counters

// Order-preserving map float -> uint32
__device__ __forceinline__ unsigned int fsort(float x) {
    unsigned int u = __float_as_uint(x);
    return (u & 0x80000000u) ? ~u : (u | 0x80000000u);
}

// software grid barrier (all blocks co-resident)
__device__ __forceinline__ void gbar(int* c, int target) {
    __syncthreads();
    if (threadIdx.x == 0) {
        __threadfence();
        atomicAdd(c, 1);
        while (__ldcg((const int*)c) < target) __nanosleep(64);
    }
    __syncthreads();
}

// analytic edge endpoints (matches _build_complex exactly)
__device__ __forceinline__ void edge_uv(int e, int& u, int& v) {
    if (e < A_NH) {
        int r = e / (WW-1), c = e % (WW-1);
        u = r * WW + c; v = u + 1;
    } else if (e < A_NH + A_NV) {
        int k = e - A_NH;
        int r = k / WW, c = k % WW;
        u = r * WW + c; v = u + WW;
    } else {
        int k = e - A_NH - A_NV;
        int r = k / (WW-1), c = k % (WW-1);
        u = r * WW + c + 1; v = (r + 1) * WW + c;
    }
}

// analytic edge -> triangle cofaces (c0==c1 iff boundary edge)
__device__ __forceinline__ void edge_cof(int e, int& c0, int& c1) {
    if (e < A_NH) {
        int r = e / (WW-1), c = e % (WW-1);
        int tA = r * (WW-1) + c;
        int tB = TRI_A + (r-1) * (WW-1) + c;
        if (r == 0)            { c0 = c1 = tA; }
        else if (r == HH-1)    { c0 = c1 = tB; }
        else                   { c0 = tA; c1 = tB; }
    } else if (e < A_NH + A_NV) {
        int k = e - A_NH;
        int r = k / WW, c = k % WW;
        int tA = r * (WW-1) + c;
        int tB = TRI_A + r * (WW-1) + (c-1);
        if (c == 0)            { c0 = c1 = tA; }
        else if (c == WW-1)    { c0 = c1 = tB; }
        else                   { c0 = tA; c1 = tB; }
    } else {
        int k = e - A_NH - A_NV;
        c0 = k;
        c1 = TRI_A + k;
    }
}

// ---------------------------------------------------------------------------
// K_PREP: fused vals+keys -> partial rank counting -> finalize (two gbars).
// ---------------------------------------------------------------------------
static constexpr int QCH = (M_S + 7) / 8;   // 1681

__global__ void __launch_bounds__(256)
k_prep(const float* __restrict__ img, float* __restrict__ out, int out_n)
{
    __shared__ u64 sk[QCH];
    int bid = blockIdx.x, tid = threadIdx.x;
    int g   = bid * 256 + tid;

    // ---- phase 1: zero output; per-simplex values + sort keys ----
    for (int o = g; o < out_n; o += PREP_BLOCKS * 256) out[o] = 0.0f;
    if (g == 0) { g_ex[N_E] = 0; g_ew[N_E] = 0; g_c3 = 0; }
    if (g < M_S) {
        int s = g;
        float v;
        if (s < N_V) {
            v = img[s];
        } else if (s < N_V + N_E) {
            int u0, v0;
            edge_uv(s - N_V, u0, v0);
            v = fmaxf(img[u0], img[v0]);
        } else {
            int t = s - N_V - N_E;
            if (t < TRI_A) {
                int rr = t / (WW-1), cc = t % (WW-1);
                int b  = rr * WW + cc;
                v = fmaxf(img[b], fmaxf(img[b+1], img[b+WW]));
            } else {
                int tt = t - TRI_A;
                int rr = tt / (WW-1), cc = tt % (WW-1);
                int b  = rr * WW + cc;
                v = fmaxf(img[b+1], fmaxf(img[b+WW], img[b+WW+1]));
            }
        }
        g_vals[s] = v;
        g_keys[s] = ((u64)fsort(v) << 32) | (unsigned int)s;
    }
    gbar(&g_c1, PREP_BLOCKS);

    // ---- phase 2: partial rank counting (q = chunk, sb = simplex block) ----
    {
        int q  = bid / 53;
        int sb = bid % 53;
        int s  = sb * 256 + tid;
        int qb = q * QCH;
        int qn = min(QCH, M_S - qb);
        for (int j = tid; j < qn; j += 256) sk[j] = g_keys[qb + j];
        __syncthreads();
        if (s < M_S) {
            u64 my = g_keys[s];
            int jLo = max(0, min(qn, N_V - qb));
            int jHi = max(jLo, min(qn, N_V + N_E - qb));
            int rank = 0, erank = 0;
            int j = 0;
            #pragma unroll 4
            for (; j < jLo; j++) rank += (sk[j] < my);
            #pragma unroll 4
            for (; j < jHi; j++) { bool lt = sk[j] < my; rank += lt; erank += lt; }
            #pragma unroll 4
            for (; j < qn; j++) rank += (sk[j] < my);
            g_prtR[q * M_S + s] = rank;
            g_prtE[q * M_S + s] = erank;
        }
    }
    gbar(&g_c2, PREP_BLOCKS);

    // ---- phase 3: finalize ----
    if (g < M_S) {
        int s = g;
        int rank = 0;
        #pragma unroll
        for (int q = 0; q < 8; q++) rank += g_prtR[q * M_S + s];
        g_rank[s] = rank;
        float myval = g_vals[s];
        g_sval[rank] = myval;
        if (rank == 0)       out[0] = myval;   // essential H0 birth
        if (rank == M_S - 1) out[1] = myval;   // its death = fmax

        if (s >= N_V && s < N_V + N_E) {
            int erank = 0;
            #pragma unroll
            for (int q = 0; q < 8; q++) erank += g_prtE[q * M_S + s];
            int e = s - N_V;
            int u, v, c0, c1;
            edge_uv(e, u, v);
            edge_cof(e, c0, c1);
            uint4 r;
            r.x = (unsigned)u | ((unsigned)v << 16);
            r.y = __float_as_uint(myval);
            r.z = (unsigned)rank;
            r.w = (unsigned)c0 | ((unsigned)c1 << 16);
            g_erec[erank] = r;
            g_ex[erank] = r.x;
            unsigned b = (c1 == c0) ? (unsigned)N_F : (unsigned)c1;
            g_ew[erank] = (unsigned)c0 | (b << 16);
        }
    }
}

// ---------------------------------------------------------------------------
// K_PAIR: grid=8, 512 threads. 32 segments per dim (4 blocks/dim, 8 segs each).
//   b0..b3: dim0 (block k bulk-hooks prefix [0, CUT32[8k]) first)
//   b4..b7: dim1 (block k bulk-hooks suffix of same size first)
// Each block: staged parallel CC -> 8 UF snapshots (u32 [root:16|comprank:16]),
// 8 concurrent serial UF threads over 32nds of the sorted edge list, then an
// 8-block software barrier and a fused parallel epilogue.
// rkm is double-buffered so the snapshot-write sweep re-inits the next stage.
// ---------------------------------------------------------------------------
static constexpr int SMEM_BYTES = (8*N1 + 4*N1) * 4 + 64;   // seg+lab+rnk+2*rkm

__device__ static const int CUT32[33] = {
       0,  210,  420,  630,  840, 1050, 1260, 1470, 1680,
    1890, 2100, 2310, 2520, 2730, 2940, 3150, 3360,
    3570, 3780, 3990, 4200, 4410, 4620, 4830, 5040,
    5250, 5460, 5670, 5880, 6090, 6300, 6510, N_E };

__device__ __forceinline__ int chase32(unsigned* L, int x) {
    int p = (int)L[x];
    while (p != x) { x = p; p = (int)L[x]; }
    return x;
}

// serial find with path halving on u32 packed words [parent:16 | rank:16]
__device__ __forceinline__ unsigned sfind(unsigned* __restrict__ sg, int x,
                                          unsigned w, int& root)
{
    for (;;) {
        int p = (int)(w >> 16);
        if (p == x) { root = x; return w; }
        unsigned wp = sg[p];
        int gp = (int)(wp >> 16);
        if (gp != p) sg[x] = (w & 0xffffu) | ((unsigned)gp << 16);
        x = p; w = wp;
    }
}

// parallel CC hooking of edge slab [lo,hi) into lab[] (min-label), full
// compression each round.
__device__ __forceinline__ void cc_hook(unsigned* lab, const unsigned* __restrict__ earr,
                                        int lo, int hi, int nnodes, int tid,
                                        int* s_changed)
{
    for (int round = 0; round < 64; round++) {
        if (tid == 0) *s_changed = 0;
        __syncthreads();
        for (int j = lo + tid; j < hi; j += 512) {
            unsigned x = earr[j];
            int ra = chase32(lab, (int)(x & 0xffffu));
            int rb = chase32(lab, (int)(x >> 16));
            if (ra != rb) {
                int mn = min(ra, rb), mx = max(ra, rb);
                atomicMin(&lab[mx], (unsigned)mn);
                *s_changed = 1;
            }
        }
        __syncthreads();
        for (int v = tid; v < nnodes; v += 512) {
            int r = (int)lab[v], pr = (int)lab[r];
            while (pr != r) { r = pr; pr = (int)lab[r]; }
            lab[v] = (unsigned)r;
        }
        __syncthreads();
        if (!*s_changed) break;
    }
}

__global__ void __launch_bounds__(512, 1)
k_pair(float* __restrict__ out)
{
    extern __shared__ unsigned smu[];
    __shared__ int s_changed;
    int tid  = threadIdx.x;
    int wid  = tid >> 5, lane = tid & 31;
    int b    = blockIdx.x;

    if (b == 0 && tid == 0) { g_c1 = 0; g_c2 = 0; }  // reset k_prep's counters

    if (b < 4) {
        // ============================ DIM 0 ============================
        unsigned* seg  = smu;                 // [8*N_V]
        unsigned* lab  = seg + 8*N_V;         // [N_V]
        unsigned* rnk  = lab + N_V;           // [N_V]
        unsigned* rkmA = rnk + N_V;           // [N_V]
        unsigned* rkmB = rkmA + N_V;          // [N_V]
        int base = b * 8;

        for (int v = tid; v < N_V; v += 512) {
            lab[v]  = (unsigned)v;
            rnk[v]  = (unsigned)g_rank[v];
            rkmA[v] = 0xffffffffu;
        }
        __syncthreads();

        for (int p = 0; p < 8; p++) {
            if (p == 0) {
                if (base > 0)   // bulk-hook prefix [0, CUT32[base])
                    cc_hook(lab, g_ex, 0, CUT32[base], N_V, tid, &s_changed);
            } else {
                cc_hook(lab, g_ex, CUT32[base+p-1], CUT32[base+p], N_V, tid, &s_changed);
            }
            unsigned* rkm = (p & 1) ? rkmB : rkmA;
            unsigned* rkn = (p & 1) ? rkmA : rkmB;
            for (int v = tid; v < N_V; v += 512)
                atomicMin(&rkm[lab[v]], rnk[v]);
            __syncthreads();
            unsigned* sg = seg + p * N_V;
            for (int v = tid; v < N_V; v += 512) {
                sg[v]  = (lab[v] << 16) | (rkm[lab[v]] & 0xffffu);
                rkn[v] = 0xffffffffu;                 // init buffer for next stage
            }
            __syncthreads();
        }

        // ---- 8 concurrent serial UF threads; dying = LARGER birth rank ----
        if (lane == 0 && wid < 8) {
            unsigned* sg = seg + wid * N_V;
            int lo = CUT32[base + wid], hi = CUT32[base + wid + 1];
            int lastIdx = -1; unsigned lastW = 0;
            unsigned x = g_ex[lo];
            int u = (int)(x & 0xffffu), v = (int)(x >> 16);
            unsigned wu = sg[u], wv = sg[v];
            for (int j = lo; j < hi; j++) {
                unsigned x2 = g_ex[j + 1];
                int un = (int)(x2 & 0xffffu), vn = (int)(x2 >> 16);
                unsigned wun = sg[un], wvn = sg[vn];
                if (u == lastIdx) wu = lastW;
                if (v == lastIdx) wv = lastW;
                int pu = (int)(wu >> 16), pv = (int)(wv >> 16);
                unsigned wpu = sg[pu], wpv = sg[pv];
                bool fu = (pu == u), fv = (pv == v);
                int ru, rv; unsigned wru, wrv;
                if (__builtin_expect((int)(((!fu) & ((int)(wpu >> 16) != pu)) |
                                           ((!fv) & ((int)(wpv >> 16) != pv))), 0)) {
                    wru = sfind(sg, u, wu, ru);
                    wrv = sfind(sg, v, wv, rv);
                } else {
                    ru = fu ? u : pu;  wru = fu ? wu : wpu;
                    rv = fv ? v : pv;  wrv = fv ? wv : wpv;
                }
                sg[u] = ((unsigned)ru << 16) | (wru & 0xffffu);
                sg[v] = ((unsigned)rv << 16) | (wrv & 0xffffu);
                bool eq = (ru == rv);
                int bu = (int)(wru & 0xffffu), bv = (int)(wrv & 0xffffu);
                bool uy = (bu > bv);
                int y = uy ? ru : rv;
                unsigned wsur = uy ? wrv : wru;
                g_dr0[j] = eq ? (ushort)0xffffu : (ushort)(uy ? bu : bv);
                sg[y] = wsur;
                lastIdx = y; lastW = wsur;
                u = un; v = vn; wu = wun; wv = wvn;
            }
        }
    } else {
        // ==================== DIM 1 (dual, reversed) ====================
        unsigned* seg  = smu;                 // [8*N1]
        unsigned* lab  = seg + 8*N1;          // [N1]
        unsigned* rnk  = lab + N1;            // [N1]
        unsigned* rkmA = rnk + N1;            // [N1]
        unsigned* rkmB = rkmA + N1;           // [N1]
        int base = (b - 4) * 8;

        for (int t = tid; t < N1; t += 512) {
            lab[t]  = (unsigned)t;
            rnk[t]  = (t < N_F) ? (unsigned)g_rank[N_V + N_E + t] : (unsigned)M_S;
            rkmA[t] = 0u;
        }
        __syncthreads();

        for (int p = 0; p < 8; p++) {
            if (p == 0) {
                if (base > 0)   // bulk-hook suffix [N_E-CUT32[base], N_E)
                    cc_hook(lab, g_ew, N_E - CUT32[base], N_E, N1, tid, &s_changed);
            } else {
                cc_hook(lab, g_ew, N_E - CUT32[base+p], N_E - CUT32[base+p-1],
                        N1, tid, &s_changed);
            }
            unsigned* rkm = (p & 1) ? rkmB : rkmA;
            unsigned* rkn = (p & 1) ? rkmA : rkmB;
            for (int t = tid; t < N1; t += 512)
                atomicMax(&rkm[lab[t]], rnk[t]);
            __syncthreads();
            unsigned* sg = seg + p * N1;
            for (int t = tid; t < N1; t += 512) {
                sg[t]  = (lab[t] << 16) | (rkm[lab[t]] & 0xffffu);
                rkn[t] = 0u;                          // init buffer for next stage
            }
            __syncthreads();
        }

        // ---- 8 concurrent serial UF threads; dying = SMALLER max rank ----
        if (lane == 0 && wid < 8) {
            unsigned* sg = seg + wid * N1;
            int q = base + wid;
            int start = N_E - CUT32[q] - 1, end = N_E - CUT32[q + 1];
            int lastIdx = -1; unsigned lastW = 0;
            unsigned x = g_ew[start];
            int a = (int)(x & 0xffffu), bn_ = (int)(x >> 16);
            unsigned wa = sg[a], wb = sg[bn_];
            for (int j = start; j >= end; j--) {
                int jn = max(j - 1, 0);
                unsigned x2 = g_ew[jn];
                int an = (int)(x2 & 0xffffu), bn = (int)(x2 >> 16);
                unsigned wan = sg[an], wbn = sg[bn];
                if (a == lastIdx)   wa = lastW;
                if (bn_ == lastIdx) wb = lastW;
                int pa = (int)(wa >> 16), pb = (int)(wb >> 16);
                unsigned wpa = sg[pa], wpb = sg[pb];
                bool fa = (pa == a), fb = (pb == bn_);
                int ra, rb; unsigned wra, wrb;
                if (__builtin_expect((int)(((!fa) & ((int)(wpa >> 16) != pa)) |
                                           ((!fb) & ((int)(wpb >> 16) != pb))), 0)) {
                    wra = sfind(sg, a, wa, ra);
                    wrb = sfind(sg, bn_, wb, rb);
                } else {
                    ra = fa ? a : pa;    wra = fa ? wa : wpa;
                    rb = fb ? bn_ : pb;  wrb = fb ? wb : wpb;
                }
                sg[a]   = ((unsigned)ra << 16) | (wra & 0xffffu);
                sg[bn_] = ((unsigned)rb << 16) | (wrb & 0xffffu);
                bool eq = (ra == rb);
                int ba = (int)(wra & 0xffffu), bbr = (int)(wrb & 0xffffu);
                bool ad = (ba < bbr);
                int y = ad ? ra : rb;
                unsigned wsur = ad ? wrb : wra;
                g_dr1[j] = eq ? (ushort)0xffffu : (ushort)(ad ? ba : bbr);
                sg[y] = wsur;
                lastIdx = y; lastW = wsur;
                a = an; bn_ = bn; wa = wan; wb = wbn;
            }
        }
    }

    // ---- 8-block barrier, then fused epilogue ----
    gbar(&g_c3, PAIR_BLOCKS);
    float2* o0 = (float2*)out;
    float2* o1 = o0 + M_S;
    for (int j = b * 512 + tid; j < N_E; j += PAIR_BLOCKS * 512) {
        uint4 r = g_erec[j];
        int d0 = g_dr0[j];
        if (d0 != 0xffff)
            o0[d0] = make_float2(g_sval[d0], __uint_as_float(r.y));
        int d1 = g_dr1[j];
        if (d1 != 0xffff)
            o1[(int)r.z] = make_float2(__uint_as_float(r.y), g_sval[d1]);
    }
}

// ---------------------------------------------------------------------------
extern "C" void kernel_launch(void* const* d_in, const int* in_sizes, int n_in,
                              void* d_out, int out_size)
{
    const float* img = (const float*)d_in[0];
    float*       out = (float*)d_out;

    cudaFuncSetAttribute(k_pair, cudaFuncAttributeMaxDynamicSharedMemorySize, SMEM_BYTES);

    k_prep<<<PREP_BLOCKS, 256>>>(img, out, out_size);
    k_pair<<<PAIR_BLOCKS, 512, SMEM_BYTES>>>(out);
}

// round 14
// speedup vs baseline: 61.5080x; 1.2286x over previous
#include <cuda_runtime.h>
#include <stdint.h>

// Problem constants (fixed-shape problem: 48x48 grid, regular triangulation)
static constexpr int HH   = 48;
static constexpr int WW   = 48;
static constexpr int N_V  = HH * WW;                                          // 2304
static constexpr int N_E  = HH*(WW-1) + (HH-1)*WW + (HH-1)*(WW-1);            // 6721
static constexpr int N_F  = 2*(HH-1)*(WW-1);                                  // 4418
static constexpr int M_S  = N_V + N_E + N_F;                                  // 13443
static constexpr int N1   = N_F + 1;                                          // 4419 dual nodes

// analytic complex constants
static constexpr int A_NH = HH*(WW-1);        // 2256 horizontal edges
static constexpr int A_NV = (HH-1)*WW;        // 2256 vertical edges
static constexpr int TRI_A = (HH-1)*(WW-1);   // 2209

static constexpr int PREP_BLOCKS = 424;       // 53 * 8
static constexpr int PAIR_BLOCKS = 16;        // 8 per dimension
static constexpr int SEGS       = 64;         // serial segments per dimension

typedef unsigned long long u64;

// Global scratch (no allocations allowed)
__device__ float    g_vals[M_S];
__device__ u64      g_keys[M_S];
__device__ int      g_rank[M_S];
__device__ float    g_sval[M_S];
__device__ int      g_prtR[8*M_S];
__device__ int      g_prtE[8*M_S];
__device__ uint4    g_erec[N_E];
__device__ unsigned g_ex[N_E + 1];     // sorted edge endpoints (u | v<<16) + sentinel
__device__ unsigned g_ew[N_E + 1];     // sorted dual endpoints (c0 | b<<16) + sentinel
__device__ ushort   g_dr0[N_E];        // dim0 dying rank per sorted edge (0xffff = none)
__device__ ushort   g_dr1[N_E];        // dim1 dying rank per sorted edge
__device__ int      g_c1 = 0, g_c2 = 0, g_c3 = 0;   // software barrier counters

// Order-preserving map float -> uint32
__device__ __forceinline__ unsigned int fsort(float x) {
    unsigned int u = __float_as_uint(x);
    return (u & 0x80000000u) ? ~u : (u | 0x80000000u);
}

// software grid barrier (all blocks co-resident)
__device__ __forceinline__ void gbar(int* c, int target) {
    __syncthreads();
    if (threadIdx.x == 0) {
        __threadfence();
        atomicAdd(c, 1);
        while (__ldcg((const int*)c) < target) __nanosleep(64);
    }
    __syncthreads();
}

// analytic edge endpoints (matches _build_complex exactly)
__device__ __forceinline__ void edge_uv(int e, int& u, int& v) {
    if (e < A_NH) {
        int r = e / (WW-1), c = e % (WW-1);
        u = r * WW + c; v = u + 1;
    } else if (e < A_NH + A_NV) {
        int k = e - A_NH;
        int r = k / WW, c = k % WW;
        u = r * WW + c; v = u + WW;
    } else {
        int k = e - A_NH - A_NV;
        int r = k / (WW-1), c = k % (WW-1);
        u = r * WW + c + 1; v = (r + 1) * WW + c;
    }
}

// analytic edge -> triangle cofaces (c0==c1 iff boundary edge)
__device__ __forceinline__ void edge_cof(int e, int& c0, int& c1) {
    if (e < A_NH) {
        int r = e / (WW-1), c = e % (WW-1);
        int tA = r * (WW-1) + c;
        int tB = TRI_A + (r-1) * (WW-1) + c;
        if (r == 0)            { c0 = c1 = tA; }
        else if (r == HH-1)    { c0 = c1 = tB; }
        else                   { c0 = tA; c1 = tB; }
    } else if (e < A_NH + A_NV) {
        int k = e - A_NH;
        int r = k / WW, c = k % WW;
        int tA = r * (WW-1) + c;
        int tB = TRI_A + r * (WW-1) + (c-1);
        if (c == 0)            { c0 = c1 = tA; }
        else if (c == WW-1)    { c0 = c1 = tB; }
        else                   { c0 = tA; c1 = tB; }
    } else {
        int k = e - A_NH - A_NV;
        c0 = k;
        c1 = TRI_A + k;
    }
}

// ---------------------------------------------------------------------------
// K_PREP: fused vals+keys -> partial rank counting -> finalize (two gbars).
// ---------------------------------------------------------------------------
static constexpr int QCH = (M_S + 7) / 8;   // 1681

__global__ void __launch_bounds__(256)
k_prep(const float* __restrict__ img, float* __restrict__ out, int out_n)
{
    __shared__ u64 sk[QCH];
    int bid = blockIdx.x, tid = threadIdx.x;
    int g   = bid * 256 + tid;

    // ---- phase 1: zero output; per-simplex values + sort keys ----
    for (int o = g; o < out_n; o += PREP_BLOCKS * 256) out[o] = 0.0f;
    if (g == 0) { g_ex[N_E] = 0; g_ew[N_E] = 0; g_c3 = 0; }
    if (g < M_S) {
        int s = g;
        float v;
        if (s < N_V) {
            v = img[s];
        } else if (s < N_V + N_E) {
            int u0, v0;
            edge_uv(s - N_V, u0, v0);
            v = fmaxf(img[u0], img[v0]);
        } else {
            int t = s - N_V - N_E;
            if (t < TRI_A) {
                int rr = t / (WW-1), cc = t % (WW-1);
                int b  = rr * WW + cc;
                v = fmaxf(img[b], fmaxf(img[b+1], img[b+WW]));
            } else {
                int tt = t - TRI_A;
                int rr = tt / (WW-1), cc = tt % (WW-1);
                int b  = rr * WW + cc;
                v = fmaxf(img[b+1], fmaxf(img[b+WW], img[b+WW+1]));
            }
        }
        g_vals[s] = v;
        g_keys[s] = ((u64)fsort(v) << 32) | (unsigned int)s;
    }
    gbar(&g_c1, PREP_BLOCKS);

    // ---- phase 2: partial rank counting (q = chunk, sb = simplex block) ----
    {
        int q  = bid / 53;
        int sb = bid % 53;
        int s  = sb * 256 + tid;
        int qb = q * QCH;
        int qn = min(QCH, M_S - qb);
        for (int j = tid; j < qn; j += 256) sk[j] = g_keys[qb + j];
        __syncthreads();
        if (s < M_S) {
            u64 my = g_keys[s];
            int jLo = max(0, min(qn, N_V - qb));
            int jHi = max(jLo, min(qn, N_V + N_E - qb));
            int rank = 0, erank = 0;
            int j = 0;
            #pragma unroll 4
            for (; j < jLo; j++) rank += (sk[j] < my);
            #pragma unroll 4
            for (; j < jHi; j++) { bool lt = sk[j] < my; rank += lt; erank += lt; }
            #pragma unroll 4
            for (; j < qn; j++) rank += (sk[j] < my);
            g_prtR[q * M_S + s] = rank;
            g_prtE[q * M_S + s] = erank;
        }
    }
    gbar(&g_c2, PREP_BLOCKS);

    // ---- phase 3: finalize ----
    if (g < M_S) {
        int s = g;
        int rank = 0;
        #pragma unroll
        for (int q = 0; q < 8; q++) rank += g_prtR[q * M_S + s];
        g_rank[s] = rank;
        float myval = g_vals[s];
        g_sval[rank] = myval;
        if (rank == 0)       out[0] = myval;   // essential H0 birth
        if (rank == M_S - 1) out[1] = myval;   // its death = fmax

        if (s >= N_V && s < N_V + N_E) {
            int erank = 0;
            #pragma unroll
            for (int q = 0; q < 8; q++) erank += g_prtE[q * M_S + s];
            int e = s - N_V;
            int u, v, c0, c1;
            edge_uv(e, u, v);
            edge_cof(e, c0, c1);
            uint4 r;
            r.x = (unsigned)u | ((unsigned)v << 16);
            r.y = __float_as_uint(myval);
            r.z = (unsigned)rank;
            r.w = (unsigned)c0 | ((unsigned)c1 << 16);
            g_erec[erank] = r;
            g_ex[erank] = r.x;
            unsigned b = (c1 == c0) ? (unsigned)N_F : (unsigned)c1;
            g_ew[erank] = (unsigned)c0 | (b << 16);
        }
    }
}

// ---------------------------------------------------------------------------
// K_PAIR: grid=16, 512 threads. 64 segments per dim (8 blocks/dim, 8 each).
// CC hooking writes ONLY two safe kinds of updates:
//   (1) hooks  atomicMin(&lab[mx], mn) at nodes OBSERVED as roots — clobbered
//       hooks are same-stage unions whose own edges re-verify until quiet;
//   (2) shortcuts atomicMin(&lab[x], chase(x)) — ancestor writes, which
//       re-root x together with its path (never split a tree).
// Writing the OTHER component's root to a non-root (R12's entry compression)
// can split a node from its old tree when the observed root is stale — old
// edges are never re-verified, so that is forbidden.
// ---------------------------------------------------------------------------
static constexpr int SMEM_BYTES = 12 * N1 * 4 + 64;   // seg[8]+lab+rnk+rkmA+rkmB

__device__ __forceinline__ int cut64(int i) { return (i >= SEGS) ? N_E : 105 * i; }

__device__ __forceinline__ int chase32(unsigned* L, int x) {
    int p = (int)L[x];
    while (p != x) { x = p; p = (int)L[x]; }
    return x;
}

// serial find with path halving on u32 packed words [parent:16 | rank:16]
__device__ __forceinline__ unsigned sfind(unsigned* __restrict__ sg, int x,
                                          unsigned w, int& root)
{
    for (;;) {
        int p = (int)(w >> 16);
        if (p == x) { root = x; return w; }
        unsigned wp = sg[p];
        int gp = (int)(wp >> 16);
        if (gp != p) sg[x] = (w & 0xffffu) | ((unsigned)gp << 16);
        x = p; w = wp;
    }
}

// sweep-free parallel CC hooking of edge slab [lo,hi). Safe-writes only
// (see header). Safe 3-barrier changed-flag protocol.
__device__ __forceinline__ void cc_hook(unsigned* lab, const unsigned* __restrict__ earr,
                                        int lo, int hi, int tid, int* s_changed)
{
    for (;;) {
        if (tid == 0) *s_changed = 0;
        __syncthreads();                       // reset visible before hooking
        for (int j = lo + tid; j < hi; j += 512) {
            unsigned x = earr[j];
            int a = (int)(x & 0xffffu), b = (int)(x >> 16);
            int ra = chase32(lab, a);
            int rb = chase32(lab, b);
            // ancestor-only shortcuts (safe: re-root x with its own path)
            atomicMin(&lab[a], (unsigned)ra);
            atomicMin(&lab[b], (unsigned)rb);
            if (ra != rb) {
                int mn = min(ra, rb), mx = max(ra, rb);
                atomicMin(&lab[mx], (unsigned)mn);   // hook at observed root
                *s_changed = 1;
            }
        }
        __syncthreads();                       // all hooking done
        bool done = (*s_changed == 0);
        __syncthreads();                       // all threads READ before next reset
        if (done) break;
    }
}

__global__ void __launch_bounds__(512, 1)
k_pair(float* __restrict__ out)
{
    extern __shared__ unsigned smu[];
    __shared__ int s_changed;
    int tid  = threadIdx.x;
    int wid  = tid >> 5, lane = tid & 31;
    int b    = blockIdx.x;

    if (b == 0 && tid == 0) { g_c1 = 0; g_c2 = 0; }  // reset k_prep's counters

    if (b < 8) {
        // ============================ DIM 0 ============================
        unsigned* seg  = smu;                 // [8*N_V]
        unsigned* lab  = seg + 8*N_V;         // [N_V]
        unsigned* rnk  = lab + N_V;           // [N_V]
        unsigned* rkmA = rnk + N_V;           // [N_V]
        unsigned* rkmB = rkmA + N_V;          // [N_V]
        int base = b * 8;

        for (int v = tid; v < N_V; v += 512) {
            lab[v]  = (unsigned)v;
            rnk[v]  = (unsigned)g_rank[v];
            rkmA[v] = 0xffffffffu;
        }
        __syncthreads();

        for (int p = 0; p < 8; p++) {
            if (p == 0) {
                if (base > 0)   // bulk-hook prefix [0, cut64(base))
                    cc_hook(lab, g_ex, 0, cut64(base), tid, &s_changed);
            } else {
                cc_hook(lab, g_ex, cut64(base+p-1), cut64(base+p), tid, &s_changed);
            }
            unsigned* rkm = (p & 1) ? rkmB : rkmA;
            unsigned* rkn = (p & 1) ? rkmA : rkmB;
            // sweep 1: full compression (store own TRUE root) + comp-min rank
            for (int v = tid; v < N_V; v += 512) {
                int r = chase32(lab, v);
                lab[v] = (unsigned)r;
                atomicMin(&rkm[r], rnk[v]);
            }
            __syncthreads();
            // sweep 2: snapshot write + init next stage's rkm buffer
            unsigned* sg = seg + p * N_V;
            for (int v = tid; v < N_V; v += 512) {
                sg[v]  = (lab[v] << 16) | (rkm[lab[v]] & 0xffffu);
                rkn[v] = 0xffffffffu;
            }
            __syncthreads();
        }

        // ---- 8 concurrent serial UF threads; dying = LARGER birth rank ----
        if (lane == 0 && wid < 8) {
            unsigned* sg = seg + wid * N_V;
            int lo = cut64(base + wid), hi = cut64(base + wid + 1);
            int lastIdx = -1; unsigned lastW = 0;
            unsigned x = g_ex[lo];
            int u = (int)(x & 0xffffu), v = (int)(x >> 16);
            unsigned wu = sg[u], wv = sg[v];
            for (int j = lo; j < hi; j++) {
                unsigned x2 = g_ex[j + 1];
                int un = (int)(x2 & 0xffffu), vn = (int)(x2 >> 16);
                unsigned wun = sg[un], wvn = sg[vn];
                if (u == lastIdx) wu = lastW;
                if (v == lastIdx) wv = lastW;
                int pu = (int)(wu >> 16), pv = (int)(wv >> 16);
                unsigned wpu = sg[pu], wpv = sg[pv];
                bool fu = (pu == u), fv = (pv == v);
                int ru, rv; unsigned wru, wrv;
                if (__builtin_expect((int)(((!fu) & ((int)(wpu >> 16) != pu)) |
                                           ((!fv) & ((int)(wpv >> 16) != pv))), 0)) {
                    wru = sfind(sg, u, wu, ru);
                    wrv = sfind(sg, v, wv, rv);
                } else {
                    ru = fu ? u : pu;  wru = fu ? wu : wpu;
                    rv = fv ? v : pv;  wrv = fv ? wv : wpv;
                }
                sg[u] = ((unsigned)ru << 16) | (wru & 0xffffu);
                sg[v] = ((unsigned)rv << 16) | (wrv & 0xffffu);
                bool eq = (ru == rv);
                int bu = (int)(wru & 0xffffu), bv = (int)(wrv & 0xffffu);
                bool uy = (bu > bv);
                int y = uy ? ru : rv;
                unsigned wsur = uy ? wrv : wru;
                g_dr0[j] = eq ? (ushort)0xffffu : (ushort)(uy ? bu : bv);
                sg[y] = wsur;
                lastIdx = y; lastW = wsur;
                u = un; v = vn; wu = wun; wv = wvn;
            }
        }
    } else {
        // ==================== DIM 1 (dual, reversed) ====================
        unsigned* seg  = smu;                 // [8*N1]
        unsigned* lab  = seg + 8*N1;          // [N1]
        unsigned* rnk  = lab + N1;            // [N1]
        unsigned* rkmA = rnk + N1;            // [N1]
        unsigned* rkmB = rkmA + N1;           // [N1]
        int base = (b - 8) * 8;

        for (int t = tid; t < N1; t += 512) {
            lab[t]  = (unsigned)t;
            rnk[t]  = (t < N_F) ? (unsigned)g_rank[N_V + N_E + t] : (unsigned)M_S;
            rkmA[t] = 0u;
        }
        __syncthreads();

        for (int p = 0; p < 8; p++) {
            if (p == 0) {
                if (base > 0)   // bulk-hook suffix [N_E-cut64(base), N_E)
                    cc_hook(lab, g_ew, N_E - cut64(base), N_E, tid, &s_changed);
            } else {
                cc_hook(lab, g_ew, N_E - cut64(base+p), N_E - cut64(base+p-1),
                        tid, &s_changed);
            }
            unsigned* rkm = (p & 1) ? rkmB : rkmA;
            unsigned* rkn = (p & 1) ? rkmA : rkmB;
            for (int t = tid; t < N1; t += 512) {
                int r = chase32(lab, t);
                lab[t] = (unsigned)r;
                atomicMax(&rkm[r], rnk[t]);
            }
            __syncthreads();
            unsigned* sg = seg + p * N1;
            for (int t = tid; t < N1; t += 512) {
                sg[t]  = (lab[t] << 16) | (rkm[lab[t]] & 0xffffu);
                rkn[t] = 0u;
            }
            __syncthreads();
        }

        // ---- 8 concurrent serial UF threads; dying = SMALLER max rank ----
        if (lane == 0 && wid < 8) {
            unsigned* sg = seg + wid * N1;
            int q = base + wid;
            int start = N_E - cut64(q) - 1, end = N_E - cut64(q + 1);
            int lastIdx = -1; unsigned lastW = 0;
            unsigned x = g_ew[start];
            int a = (int)(x & 0xffffu), bn_ = (int)(x >> 16);
            unsigned wa = sg[a], wb = sg[bn_];
            for (int j = start; j >= end; j--) {
                int jn = max(j - 1, 0);
                unsigned x2 = g_ew[jn];
                int an = (int)(x2 & 0xffffu), bn = (int)(x2 >> 16);
                unsigned wan = sg[an], wbn = sg[bn];
                if (a == lastIdx)   wa = lastW;
                if (bn_ == lastIdx) wb = lastW;
                int pa = (int)(wa >> 16), pb = (int)(wb >> 16);
                unsigned wpa = sg[pa], wpb = sg[pb];
                bool fa = (pa == a), fb = (pb == bn_);
                int ra, rb; unsigned wra, wrb;
                if (__builtin_expect((int)(((!fa) & ((int)(wpa >> 16) != pa)) |
                                           ((!fb) & ((int)(wpb >> 16) != pb))), 0)) {
                    wra = sfind(sg, a, wa, ra);
                    wrb = sfind(sg, bn_, wb, rb);
                } else {
                    ra = fa ? a : pa;    wra = fa ? wa : wpa;
                    rb = fb ? bn_ : pb;  wrb = fb ? wb : wpb;
                }
                sg[a]   = ((unsigned)ra << 16) | (wra & 0xffffu);
                sg[bn_] = ((unsigned)rb << 16) | (wrb & 0xffffu);
                bool eq = (ra == rb);
                int ba = (int)(wra & 0xffffu), bbr = (int)(wrb & 0xffffu);
                bool ad = (ba < bbr);
                int y = ad ? ra : rb;
                unsigned wsur = ad ? wrb : wra;
                g_dr1[j] = eq ? (ushort)0xffffu : (ushort)(ad ? ba : bbr);
                sg[y] = wsur;
                lastIdx = y; lastW = wsur;
                a = an; bn_ = bn; wa = wan; wb = wbn;
            }
        }
    }

    // ---- 16-block barrier, then fused epilogue ----
    gbar(&g_c3, PAIR_BLOCKS);
    float2* o0 = (float2*)out;
    float2* o1 = o0 + M_S;
    for (int j = b * 512 + tid; j < N_E; j += PAIR_BLOCKS * 512) {
        uint4 r = g_erec[j];
        int d0 = g_dr0[j];
        if (d0 != 0xffff)
            o0[d0] = make_float2(g_sval[d0], __uint_as_float(r.y));
        int d1 = g_dr1[j];
        if (d1 != 0xffff)
            o1[(int)r.z] = make_float2(__uint_as_float(r.y), g_sval[d1]);
    }
}

// ---------------------------------------------------------------------------
extern "C" void kernel_launch(void* const* d_in, const int* in_sizes, int n_in,
                              void* d_out, int out_size)
{
    const float* img = (const float*)d_in[0];
    float*       out = (float*)d_out;

    cudaFuncSetAttribute(k_pair, cudaFuncAttributeMaxDynamicSharedMemorySize, SMEM_BYTES);

    k_prep<<<PREP_BLOCKS, 256>>>(img, out, out_size);
    k_pair<<<PAIR_BLOCKS, 512, SMEM_BYTES>>>(out);
}